// round 3
// baseline (speedup 1.0000x reference)
#include <cuda_runtime.h>
#include <cuda_fp16.h>
#include <cuda_bf16.h>

// RoadGNN: GCN(2->32) -> ReLU -> GAT(32->2x32, mean heads) -> ReLU -> GCN(32->1)
// CSR gather, single-pass GAT with global-max softmax shift, fp16 hg gathers.

#define MAXN 100000
#define MAXE 1600000

// ---------------- scratch (device globals; no allocations) ----------------
__device__ int      g_deg[MAXN];
__device__ int      g_off[MAXN];
__device__ int      g_cur[MAXN];
__device__ int      g_csr[MAXE];
__device__ int      g_bsum[128];
__device__ float    g_dinv[MAXN];
__device__ float    g_hs[MAXN * 32];     // dinv[n] * (x@W1)[n]  (fp32)
__device__ __half   g_hgh[MAXN * 64];    // GAT linear output, fp16
__device__ float    g_asrc[MAXN * 2];
__device__ float    g_adst[MAXN * 2];
__device__ unsigned g_gmaxe[2];          // global max of a_src per head (order-encoded)
__device__ float    g_z[MAXN];
__device__ int      g_is64;

// ---------------- helpers ----------------
__device__ __forceinline__ float lrelu(float v) { return v > 0.f ? v : 0.2f * v; }
__device__ __forceinline__ unsigned encf(float f) {
    unsigned u = __float_as_uint(f);
    return (u & 0x80000000u) ? ~u : (u | 0x80000000u);
}
__device__ __forceinline__ float decf(unsigned u) {
    return __uint_as_float((u & 0x80000000u) ? (u & 0x7fffffffu) : ~u);
}
__device__ __forceinline__ void load_edge(const void* ei, int e, int E, int& r, int& c) {
    if (g_is64) {
        const long long* p = (const long long*)ei;
        r = (int)p[e]; c = (int)p[E + e];
    } else {
        const int* p = (const int*)ei;
        r = p[e]; c = p[E + e];
    }
}

// ---------------- kernels ----------------

// zero + dtype detect + gmax init
__global__ void k_zero(const int* __restrict__ ei32, int n) {
    int gid = blockIdx.x * blockDim.x + threadIdx.x;
    if (gid < n) { g_deg[gid] = 0; g_cur[gid] = 0; }
    if (gid == 0) {
        int is64 = 1;
        for (int i = 0; i < 64; i++)
            if (ei32[2 * i + 1] != 0) { is64 = 0; break; }
        g_is64 = is64;
        g_gmaxe[0] = 0u; g_gmaxe[1] = 0u;
    }
}

__global__ void k_degcount(const void* __restrict__ ei, int E) {
    int e = blockIdx.x * blockDim.x + threadIdx.x;
    if (e >= E) return;
    int r, c; load_edge(ei, e, E, r, c);
    atomicAdd(&g_deg[c], 1);
}

// exclusive prefix scan of g_deg into g_off: 3 stages.
__global__ void k_scan1(int n) {
    __shared__ int sh[1024];
    int tid = threadIdx.x;
    int i = blockIdx.x * 1024 + tid;
    int v = (i < n) ? g_deg[i] : 0;
    sh[tid] = v;
    __syncthreads();
#pragma unroll
    for (int d = 1; d < 1024; d <<= 1) {
        int t = (tid >= d) ? sh[tid - d] : 0;
        __syncthreads();
        sh[tid] += t;
        __syncthreads();
    }
    if (i < n) g_off[i] = sh[tid] - v;
    if (tid == 1023) g_bsum[blockIdx.x] = sh[1023];
}

__global__ void k_scan2(int nb) {
    if (threadIdx.x == 0) {
        int run = 0;
        for (int b = 0; b < nb; b++) { int t = g_bsum[b]; g_bsum[b] = run; run += t; }
    }
}

__global__ void k_scan3(int n) {
    int i = blockIdx.x * 1024 + threadIdx.x;
    if (i < n) g_off[i] += g_bsum[blockIdx.x];
}

__global__ void k_fill(const void* __restrict__ ei, int E) {
    int e = blockIdx.x * blockDim.x + threadIdx.x;
    if (e >= E) return;
    int r, c; load_edge(ei, e, E, r, c);
    int pos = g_off[c] + atomicAdd(&g_cur[c], 1);
    g_csr[pos] = r;
}

__global__ void k_node1(const float* __restrict__ x, const float* __restrict__ W1, int n) {
    int gid = blockIdx.x * blockDim.x + threadIdx.x;
    if (gid >= n * 32) return;
    int node = gid >> 5, k = gid & 31;
    float d = rsqrtf((float)(g_deg[node] + 1));
    if (k == 0) g_dinv[node] = d;
    float hp = fmaf(x[2 * node], W1[k], x[2 * node + 1] * W1[32 + k]);
    g_hs[gid] = d * hp;
}

// warp per node: GCN1 gather (unroll 4) + relu, GAT linear, attention dots,
// block-reduced global max of a_src.
__global__ void k_layer1(const float* __restrict__ Wg, const float* __restrict__ b1,
                         const float* __restrict__ attS, const float* __restrict__ attD, int n) {
    __shared__ float sWg[32 * 64];
    __shared__ unsigned smax[2];
    int tid = threadIdx.x;
    for (int i = tid; i < 2048; i += blockDim.x) sWg[i] = Wg[i];
    if (tid < 2) smax[tid] = 0u;
    __syncthreads();

    int node = (blockIdx.x * blockDim.x + tid) >> 5;
    int lane = tid & 31;
    if (node < n) {
        float a0 = g_hs[node * 32 + lane];   // self loop
        float a1 = 0.f, a2 = 0.f, a3 = 0.f;
        int off = g_off[node], end = off + g_deg[node];
        int j = off;
        for (; j + 3 < end; j += 4) {
            int r0 = g_csr[j], r1 = g_csr[j + 1], r2 = g_csr[j + 2], r3 = g_csr[j + 3];
            a0 += g_hs[r0 * 32 + lane];
            a1 += g_hs[r1 * 32 + lane];
            a2 += g_hs[r2 * 32 + lane];
            a3 += g_hs[r3 * 32 + lane];
        }
        for (; j < end; j++) a0 += g_hs[g_csr[j] * 32 + lane];
        float acc = (a0 + a1) + (a2 + a3);

        float h1 = fmaxf(fmaf(g_dinv[node], acc, b1[lane]), 0.f);

        float o0 = 0.f, o1 = 0.f;
#pragma unroll
        for (int i = 0; i < 32; i++) {
            float hv = __shfl_sync(0xffffffffu, h1, i);
            o0 = fmaf(hv, sWg[i * 64 + lane], o0);
            o1 = fmaf(hv, sWg[i * 64 + 32 + lane], o1);
        }
        g_hgh[node * 64 + lane]      = __float2half(o0);
        g_hgh[node * 64 + 32 + lane] = __float2half(o1);

        float as0 = o0 * attS[lane];
        float as1 = o1 * attS[32 + lane];
        float ad0 = o0 * attD[lane];
        float ad1 = o1 * attD[32 + lane];
#pragma unroll
        for (int o = 16; o; o >>= 1) {
            as0 += __shfl_down_sync(0xffffffffu, as0, o);
            as1 += __shfl_down_sync(0xffffffffu, as1, o);
            ad0 += __shfl_down_sync(0xffffffffu, ad0, o);
            ad1 += __shfl_down_sync(0xffffffffu, ad1, o);
        }
        if (lane == 0) {
            g_asrc[node * 2]     = as0;
            g_asrc[node * 2 + 1] = as1;
            g_adst[node * 2]     = ad0;
            g_adst[node * 2 + 1] = ad1;
            atomicMax(&smax[0], encf(as0));
            atomicMax(&smax[1], encf(as1));
        }
    }
    __syncthreads();
    if (tid < 2) atomicMax(&g_gmaxe[tid], smax[tid]);
}

// one 64-thread block per node; warp h handles head h. Single pass:
// m = lrelu(gmax_h + a_dst) is a valid upper bound on all edge e's (lrelu monotone).
__global__ void k_gat(const float* __restrict__ gat_b, const float* __restrict__ W2, int n) {
    __shared__ float shv[2][32];
    int node = blockIdx.x;
    int h = threadIdx.x >> 5;
    int lane = threadIdx.x & 31;

    float ad = g_adst[2 * node + h];
    float m  = lrelu(decf(g_gmaxe[h]) + ad);
    float es = lrelu(g_asrc[2 * node + h] + ad);
    float exs = __expf(es - m);
    float s = exs;
    float acc = exs * __half2float(g_hgh[node * 64 + h * 32 + lane]);

    int off = g_off[node], end = off + g_deg[node];
#pragma unroll 4
    for (int j = off; j < end; j++) {
        int r = g_csr[j];
        float as = g_asrc[2 * r + h];
        float ex = __expf(lrelu(as + ad) - m);
        acc = fmaf(ex, __half2float(g_hgh[r * 64 + h * 32 + lane]), acc);
        s += ex;
    }
    shv[h][lane] = acc / s;
    __syncthreads();

    if (h == 0) {
        float h2 = fmaxf(fmaf(0.5f, shv[0][lane] + shv[1][lane], gat_b[lane]), 0.f);
        float zi = h2 * W2[lane];
#pragma unroll
        for (int o = 16; o; o >>= 1)
            zi += __shfl_down_sync(0xffffffffu, zi, o);
        if (lane == 0) g_z[node] = g_dinv[node] * zi;
    }
}

// warp per node: GCN2 gather + output
__global__ void k_gcn2(float* __restrict__ out, const float* __restrict__ b2, int n) {
    int tid = threadIdx.x;
    int node = (blockIdx.x * blockDim.x + tid) >> 5;
    int lane = tid & 31;
    if (node >= n) return;
    float s = (lane == 0) ? g_z[node] : 0.f;
    int off = g_off[node], end = off + g_deg[node];
    for (int j = off + lane; j < end; j += 32)
        s += g_z[g_csr[j]];
#pragma unroll
    for (int o = 16; o; o >>= 1)
        s += __shfl_down_sync(0xffffffffu, s, o);
    if (lane == 0) out[node] = fmaf(g_dinv[node], s, b2[0]);
}

// ---------------- launch ----------------
extern "C" void kernel_launch(void* const* d_in, const int* in_sizes, int n_in,
                              void* d_out, int out_size) {
    const float* x    = (const float*)d_in[0];
    const void*  ei   = d_in[1];
    const float* W1   = (const float*)d_in[2];
    const float* b1   = (const float*)d_in[3];
    const float* Wg   = (const float*)d_in[4];
    const float* attS = (const float*)d_in[5];
    const float* attD = (const float*)d_in[6];
    const float* gb   = (const float*)d_in[7];
    const float* W2   = (const float*)d_in[8];
    const float* b2   = (const float*)d_in[9];
    float* out = (float*)d_out;

    int n = in_sizes[0] / 2;
    int E = in_sizes[1] / 2;
    const int T = 256;
    int nb = (n + 1023) / 1024;

    k_zero<<<(n + T - 1) / T, T>>>((const int*)ei, n);
    k_degcount<<<(E + T - 1) / T, T>>>(ei, E);
    k_scan1<<<nb, 1024>>>(n);
    k_scan2<<<1, 32>>>(nb);
    k_scan3<<<nb, 1024>>>(n);
    k_fill<<<(E + T - 1) / T, T>>>(ei, E);
    k_node1<<<(n * 32 + T - 1) / T, T>>>(x, W1, n);
    k_layer1<<<(n * 32 + T - 1) / T, T>>>(Wg, b1, attS, attD, n);
    k_gat<<<n, 64>>>(gb, W2, n);
    k_gcn2<<<(n * 32 + T - 1) / T, T>>>(out, b2, n);
}

// round 4
// speedup vs baseline: 1.1661x; 1.1661x over previous
#include <cuda_runtime.h>
#include <cuda_fp16.h>
#include <cuda_bf16.h>

// RoadGNN: GCN(2->32) -> ReLU -> GAT(32->2x32, mean heads) -> ReLU -> GCN(32->1)
// CSR gather; GAT softmax weights precomputed edge-parallel; fp16 hg gathers.

#define MAXN 100000
#define MAXE 1600000

// ---------------- scratch ----------------
__device__ int      g_deg[MAXN];
__device__ int      g_off[MAXN];
__device__ int      g_cur[MAXN];
__device__ int      g_csr[MAXE];        // src ids grouped by dst
__device__ int      g_dst[MAXE];        // dst id per CSR slot
__device__ float    g_ex[MAXE * 2];     // per-edge softmax numerators (2 heads)
__device__ int      g_bsum[128];
__device__ float    g_dinv[MAXN];
__device__ float    g_hs[MAXN * 32];    // dinv[n] * (x@W1)[n]
__device__ __half   g_hgh[MAXN * 64];   // GAT linear output fp16: [0..31]=h0, [32..63]=h1
__device__ float    g_asrc[MAXN * 2];
__device__ float    g_adst[MAXN * 2];
__device__ unsigned g_gmaxe[2];
__device__ float    g_z[MAXN];
__device__ int      g_is64;

// ---------------- helpers ----------------
__device__ __forceinline__ float lrelu(float v) { return v > 0.f ? v : 0.2f * v; }
__device__ __forceinline__ unsigned encf(float f) {
    unsigned u = __float_as_uint(f);
    return (u & 0x80000000u) ? ~u : (u | 0x80000000u);
}
__device__ __forceinline__ float decf(unsigned u) {
    return __uint_as_float((u & 0x80000000u) ? (u & 0x7fffffffu) : ~u);
}
__device__ __forceinline__ void load_edge(const void* ei, int e, int E, int& r, int& c) {
    if (g_is64) {
        const long long* p = (const long long*)ei;
        r = (int)p[e]; c = (int)p[E + e];
    } else {
        const int* p = (const int*)ei;
        r = p[e]; c = p[E + e];
    }
}

// ---------------- kernels ----------------
__global__ void k_zero(const int* __restrict__ ei32, int n) {
    int gid = blockIdx.x * blockDim.x + threadIdx.x;
    if (gid < n) { g_deg[gid] = 0; g_cur[gid] = 0; }
    if (gid == 0) {
        int is64 = 1;
        for (int i = 0; i < 64; i++)
            if (ei32[2 * i + 1] != 0) { is64 = 0; break; }
        g_is64 = is64;
        g_gmaxe[0] = 0u; g_gmaxe[1] = 0u;
    }
}

__global__ void k_degcount(const void* __restrict__ ei, int E) {
    int e = blockIdx.x * blockDim.x + threadIdx.x;
    if (e >= E) return;
    int r, c; load_edge(ei, e, E, r, c);
    atomicAdd(&g_deg[c], 1);
}

__global__ void k_scan1(int n) {
    __shared__ int sh[1024];
    int tid = threadIdx.x;
    int i = blockIdx.x * 1024 + tid;
    int v = (i < n) ? g_deg[i] : 0;
    sh[tid] = v;
    __syncthreads();
#pragma unroll
    for (int d = 1; d < 1024; d <<= 1) {
        int t = (tid >= d) ? sh[tid - d] : 0;
        __syncthreads();
        sh[tid] += t;
        __syncthreads();
    }
    if (i < n) g_off[i] = sh[tid] - v;
    if (tid == 1023) g_bsum[blockIdx.x] = sh[1023];
}

// warp shfl-scan over <=128 block sums
__global__ void k_scan2(int nb) {
    int lane = threadIdx.x;
    int carry = 0;
    for (int base = 0; base < nb; base += 32) {
        int idx = base + lane;
        int v = (idx < nb) ? g_bsum[idx] : 0;
        int orig = v;
#pragma unroll
        for (int o = 1; o < 32; o <<= 1) {
            int t = __shfl_up_sync(0xffffffffu, v, o);
            if (lane >= o) v += t;
        }
        int tot = __shfl_sync(0xffffffffu, v, 31);
        if (idx < nb) g_bsum[idx] = v - orig + carry;
        carry += tot;
    }
}

__global__ void k_scan3(int n) {
    int i = blockIdx.x * 1024 + threadIdx.x;
    if (i < n) g_off[i] += g_bsum[blockIdx.x];
}

__global__ void k_fill(const void* __restrict__ ei, int E) {
    int e = blockIdx.x * blockDim.x + threadIdx.x;
    if (e >= E) return;
    int r, c; load_edge(ei, e, E, r, c);
    int pos = g_off[c] + atomicAdd(&g_cur[c], 1);
    g_csr[pos] = r;
    g_dst[pos] = c;
}

__global__ void k_node1(const float* __restrict__ x, const float* __restrict__ W1, int n) {
    int gid = blockIdx.x * blockDim.x + threadIdx.x;
    if (gid >= n * 32) return;
    int node = gid >> 5, k = gid & 31;
    float d = rsqrtf((float)(g_deg[node] + 1));
    if (k == 0) g_dinv[node] = d;
    float hp = fmaf(x[2 * node], W1[k], x[2 * node + 1] * W1[32 + k]);
    g_hs[gid] = d * hp;
}

// warp per node: GCN1 gather + relu, GAT linear, attention dots, global max.
__global__ void k_layer1(const float* __restrict__ Wg, const float* __restrict__ b1,
                         const float* __restrict__ attS, const float* __restrict__ attD, int n) {
    __shared__ float sWg[32 * 64];
    __shared__ unsigned smax[2];
    int tid = threadIdx.x;
    for (int i = tid; i < 2048; i += blockDim.x) sWg[i] = Wg[i];
    if (tid < 2) smax[tid] = 0u;
    __syncthreads();

    int node = (blockIdx.x * blockDim.x + tid) >> 5;
    int lane = tid & 31;
    if (node < n) {
        float a0 = g_hs[node * 32 + lane];
        float a1 = 0.f, a2 = 0.f, a3 = 0.f;
        int off = g_off[node], end = off + g_deg[node];
        int j = off;
        for (; j + 3 < end; j += 4) {
            int r0 = g_csr[j], r1 = g_csr[j + 1], r2 = g_csr[j + 2], r3 = g_csr[j + 3];
            a0 += g_hs[r0 * 32 + lane];
            a1 += g_hs[r1 * 32 + lane];
            a2 += g_hs[r2 * 32 + lane];
            a3 += g_hs[r3 * 32 + lane];
        }
        for (; j < end; j++) a0 += g_hs[g_csr[j] * 32 + lane];
        float acc = (a0 + a1) + (a2 + a3);

        float h1 = fmaxf(fmaf(g_dinv[node], acc, b1[lane]), 0.f);

        float o0 = 0.f, o1 = 0.f;
#pragma unroll
        for (int i = 0; i < 32; i++) {
            float hv = __shfl_sync(0xffffffffu, h1, i);
            o0 = fmaf(hv, sWg[i * 64 + lane], o0);
            o1 = fmaf(hv, sWg[i * 64 + 32 + lane], o1);
        }
        g_hgh[node * 64 + lane]      = __float2half(o0);
        g_hgh[node * 64 + 32 + lane] = __float2half(o1);

        float as0 = o0 * attS[lane];
        float as1 = o1 * attS[32 + lane];
        float ad0 = o0 * attD[lane];
        float ad1 = o1 * attD[32 + lane];
#pragma unroll
        for (int o = 16; o; o >>= 1) {
            as0 += __shfl_down_sync(0xffffffffu, as0, o);
            as1 += __shfl_down_sync(0xffffffffu, as1, o);
            ad0 += __shfl_down_sync(0xffffffffu, ad0, o);
            ad1 += __shfl_down_sync(0xffffffffu, ad1, o);
        }
        if (lane == 0) {
            g_asrc[node * 2]     = as0;
            g_asrc[node * 2 + 1] = as1;
            g_adst[node * 2]     = ad0;
            g_adst[node * 2 + 1] = ad1;
            atomicMax(&smax[0], encf(as0));
            atomicMax(&smax[1], encf(as1));
        }
    }
    __syncthreads();
    if (tid < 2) atomicMax(&g_gmaxe[tid], smax[tid]);
}

// edge-parallel: softmax numerators for both heads, CSR order, coalesced.
__global__ void k_edgeex(int E) {
    int j = blockIdx.x * blockDim.x + threadIdx.x;
    if (j >= E) return;
    int r = g_csr[j], c = g_dst[j];
    float2 as = *(const float2*)&g_asrc[2 * r];
    float2 ad = *(const float2*)&g_adst[2 * c];
    float m0 = lrelu(decf(g_gmaxe[0]) + ad.x);
    float m1 = lrelu(decf(g_gmaxe[1]) + ad.y);
    float2 ex;
    ex.x = __expf(lrelu(as.x + ad.x) - m0);
    ex.y = __expf(lrelu(as.y + ad.y) - m1);
    *(float2*)&g_ex[2 * j] = ex;
}

// warp per node: lanes 0-15 = head0 channel pairs, lanes 16-31 = head1.
// Per edge: one 128B fp16 load + broadcast ex, 2 FMAs per lane.
__global__ void k_gat(const float* __restrict__ gat_b, const float* __restrict__ W2, int n) {
    int tid = threadIdx.x;
    int node = (blockIdx.x * blockDim.x + tid) >> 5;
    int lane = tid & 31;
    if (node >= n) return;
    bool head1 = lane >= 16;
    int ch = (lane & 15) * 2;
    const unsigned* hgu = (const unsigned*)g_hgh;

    float2 ad = *(const float2*)&g_adst[2 * node];
    float2 as = *(const float2*)&g_asrc[2 * node];
    float m   = head1 ? lrelu(decf(g_gmaxe[1]) + ad.y) : lrelu(decf(g_gmaxe[0]) + ad.x);
    float es  = head1 ? lrelu(as.y + ad.y) : lrelu(as.x + ad.x);
    float exs = __expf(es - m);

    unsigned hv = hgu[node * 32 + lane];
    float2 hf = __half22float2(*(const __half2*)&hv);
    float sA = exs, sB = 0.f;
    float accx = exs * hf.x, accy = exs * hf.y;
    float acc2x = 0.f, acc2y = 0.f;

    int off = g_off[node], end = off + g_deg[node];
    int j = off;
    for (; j + 1 < end; j += 2) {
        int r0 = g_csr[j], r1 = g_csr[j + 1];
        float2 e0 = *(const float2*)&g_ex[2 * j];
        float2 e1 = *(const float2*)&g_ex[2 * j + 2];
        unsigned h0 = hgu[r0 * 32 + lane];
        unsigned h1 = hgu[r1 * 32 + lane];
        float w0 = head1 ? e0.y : e0.x;
        float w1 = head1 ? e1.y : e1.x;
        float2 f0 = __half22float2(*(const __half2*)&h0);
        float2 f1 = __half22float2(*(const __half2*)&h1);
        accx  = fmaf(w0, f0.x, accx);
        accy  = fmaf(w0, f0.y, accy);
        acc2x = fmaf(w1, f1.x, acc2x);
        acc2y = fmaf(w1, f1.y, acc2y);
        sA += w0; sB += w1;
    }
    if (j < end) {
        int r0 = g_csr[j];
        float2 e0 = *(const float2*)&g_ex[2 * j];
        unsigned h0 = hgu[r0 * 32 + lane];
        float w0 = head1 ? e0.y : e0.x;
        float2 f0 = __half22float2(*(const __half2*)&h0);
        accx = fmaf(w0, f0.x, accx);
        accy = fmaf(w0, f0.y, accy);
        sA += w0;
    }
    float s = sA + sB;
    float vx = (accx + acc2x) / s;
    float vy = (accy + acc2y) / s;

    // combine heads: lane<16 holds head0, lane+16 holds head1 (same channels)
    float ox = __shfl_down_sync(0xffffffffu, vx, 16);
    float oy = __shfl_down_sync(0xffffffffu, vy, 16);
    float c0 = fmaxf(fmaf(0.5f, vx + ox, gat_b[ch]),     0.f);
    float c1 = fmaxf(fmaf(0.5f, vy + oy, gat_b[ch + 1]), 0.f);
    float zi = fmaf(c0, W2[ch], c1 * W2[ch + 1]);
#pragma unroll
    for (int o = 8; o; o >>= 1)
        zi += __shfl_down_sync(0xffffffffu, zi, o);
    if (lane == 0) g_z[node] = g_dinv[node] * zi;
}

__global__ void k_gcn2(float* __restrict__ out, const float* __restrict__ b2, int n) {
    int tid = threadIdx.x;
    int node = (blockIdx.x * blockDim.x + tid) >> 5;
    int lane = tid & 31;
    if (node >= n) return;
    float s = (lane == 0) ? g_z[node] : 0.f;
    int off = g_off[node], end = off + g_deg[node];
    for (int j = off + lane; j < end; j += 32)
        s += g_z[g_csr[j]];
#pragma unroll
    for (int o = 16; o; o >>= 1)
        s += __shfl_down_sync(0xffffffffu, s, o);
    if (lane == 0) out[node] = fmaf(g_dinv[node], s, b2[0]);
}

// ---------------- launch ----------------
extern "C" void kernel_launch(void* const* d_in, const int* in_sizes, int n_in,
                              void* d_out, int out_size) {
    const float* x    = (const float*)d_in[0];
    const void*  ei   = d_in[1];
    const float* W1   = (const float*)d_in[2];
    const float* b1   = (const float*)d_in[3];
    const float* Wg   = (const float*)d_in[4];
    const float* attS = (const float*)d_in[5];
    const float* attD = (const float*)d_in[6];
    const float* gb   = (const float*)d_in[7];
    const float* W2   = (const float*)d_in[8];
    const float* b2   = (const float*)d_in[9];
    float* out = (float*)d_out;

    int n = in_sizes[0] / 2;
    int E = in_sizes[1] / 2;
    const int T = 256;
    int nb = (n + 1023) / 1024;

    k_zero<<<(n + T - 1) / T, T>>>((const int*)ei, n);
    k_degcount<<<(E + T - 1) / T, T>>>(ei, E);
    k_scan1<<<nb, 1024>>>(n);
    k_scan2<<<1, 32>>>(nb);
    k_scan3<<<nb, 1024>>>(n);
    k_fill<<<(E + T - 1) / T, T>>>(ei, E);
    k_node1<<<(n * 32 + T - 1) / T, T>>>(x, W1, n);
    k_layer1<<<(n * 32 + T - 1) / T, T>>>(Wg, b1, attS, attD, n);
    k_edgeex<<<(E + T - 1) / T, T>>>(E);
    k_gat<<<(n * 32 + T - 1) / T, T>>>(gb, W2, n);
    k_gcn2<<<(n * 32 + T - 1) / T, T>>>(out, b2, n);
}

// round 5
// speedup vs baseline: 1.1989x; 1.0282x over previous
#include <cuda_runtime.h>
#include <cuda_fp16.h>
#include <cuda_bf16.h>

// RoadGNN: GCN(2->32) -> ReLU -> GAT(32->2x32, mean heads) -> ReLU -> GCN(32->1)
// CSR gather (segments padded to 4 for vector index loads), fp16 feature gathers,
// edge-parallel softmax weights.

#define MAXN 100000
#define MAXE 1600000
#define MAXEP (MAXE + 3 * MAXN)   // padded CSR capacity

// ---------------- scratch ----------------
__device__ int      g_deg[MAXN];
__device__ int      g_off[MAXN];                 // padded exclusive offsets (mult of 4)
__device__ int      g_cur[MAXN];
__device__ __align__(16) int2  g_edge[MAXEP];    // (src,dst) per CSR slot
__device__ __align__(16) float g_ex[MAXEP * 2];  // per-edge softmax numerators (2 heads)
__device__ int      g_bsum[128];
__device__ int      g_total;                     // padded total slots
__device__ float    g_dinv[MAXN];
__device__ __half   g_hs[MAXN * 32];             // dinv[n]*(x@W1)[n], fp16
__device__ __half   g_hgh[MAXN * 64];            // GAT linear out fp16 (h0|h1)
__device__ float    g_asrc[MAXN * 2];
__device__ float    g_adst[MAXN * 2];
__device__ unsigned g_gmaxe[2];
__device__ float    g_z[MAXN];
__device__ int      g_is64;

// ---------------- helpers ----------------
__device__ __forceinline__ float lrelu(float v) { return v > 0.f ? v : 0.2f * v; }
__device__ __forceinline__ unsigned encf(float f) {
    unsigned u = __float_as_uint(f);
    return (u & 0x80000000u) ? ~u : (u | 0x80000000u);
}
__device__ __forceinline__ float decf(unsigned u) {
    return __uint_as_float((u & 0x80000000u) ? (u & 0x7fffffffu) : ~u);
}
__device__ __forceinline__ void load_edge(const void* ei, int e, int E, int& r, int& c) {
    if (g_is64) {
        const long long* p = (const long long*)ei;
        r = (int)p[e]; c = (int)p[E + e];
    } else {
        const int* p = (const int*)ei;
        r = p[e]; c = p[E + e];
    }
}

// ---------------- kernels ----------------
__global__ void k_zero(const int* __restrict__ ei32, int n, int ep) {
    int gid = blockIdx.x * blockDim.x + threadIdx.x;
    if (gid < n) { g_deg[gid] = 0; g_cur[gid] = 0; }
    if (gid < ep) g_edge[gid] = make_int2(0, 0);
    if (gid == 0) {
        int is64 = 1;
        for (int i = 0; i < 64; i++)
            if (ei32[2 * i + 1] != 0) { is64 = 0; break; }
        g_is64 = is64;
        g_gmaxe[0] = 0u; g_gmaxe[1] = 0u;
    }
}

// count in-degree; reads only the col half of edge_index
__global__ void k_degcount(const void* __restrict__ ei, int E) {
    int e = blockIdx.x * blockDim.x + threadIdx.x;
    if (e >= E) return;
    int c;
    if (g_is64) c = (int)((const long long*)ei)[E + e];
    else        c = ((const int*)ei)[E + e];
    atomicAdd(&g_deg[c], 1);
}

// scan of 4-padded degrees
__global__ void k_scan1(int n) {
    __shared__ int sh[1024];
    int tid = threadIdx.x;
    int i = blockIdx.x * 1024 + tid;
    int v = (i < n) ? ((g_deg[i] + 3) & ~3) : 0;
    sh[tid] = v;
    __syncthreads();
#pragma unroll
    for (int d = 1; d < 1024; d <<= 1) {
        int t = (tid >= d) ? sh[tid - d] : 0;
        __syncthreads();
        sh[tid] += t;
        __syncthreads();
    }
    if (i < n) g_off[i] = sh[tid] - v;
    if (tid == 1023) g_bsum[blockIdx.x] = sh[1023];
}

__global__ void k_scan2(int nb) {
    int lane = threadIdx.x;
    int carry = 0;
    for (int base = 0; base < nb; base += 32) {
        int idx = base + lane;
        int v = (idx < nb) ? g_bsum[idx] : 0;
        int orig = v;
#pragma unroll
        for (int o = 1; o < 32; o <<= 1) {
            int t = __shfl_up_sync(0xffffffffu, v, o);
            if (lane >= o) v += t;
        }
        int tot = __shfl_sync(0xffffffffu, v, 31);
        if (idx < nb) g_bsum[idx] = v - orig + carry;
        carry += tot;
    }
    if (lane == 0) g_total = carry;
}

__global__ void k_scan3(int n) {
    int i = blockIdx.x * 1024 + threadIdx.x;
    if (i < n) g_off[i] += g_bsum[blockIdx.x];
}

__global__ void k_fill(const void* __restrict__ ei, int E) {
    int e = blockIdx.x * blockDim.x + threadIdx.x;
    if (e >= E) return;
    int r, c; load_edge(ei, e, E, r, c);
    int pos = g_off[c] + atomicAdd(&g_cur[c], 1);
    g_edge[pos] = make_int2(r, c);
}

__global__ void k_node1(const float* __restrict__ x, const float* __restrict__ W1, int n) {
    int gid = blockIdx.x * blockDim.x + threadIdx.x;
    if (gid >= n * 32) return;
    int node = gid >> 5, k = gid & 31;
    float d = rsqrtf((float)(g_deg[node] + 1));
    if (k == 0) g_dinv[node] = d;
    float hp = fmaf(x[2 * node], W1[k], x[2 * node + 1] * W1[32 + k]);
    g_hs[gid] = __float2half(d * hp);
}

// warp per node: GCN1 gather (fp16, int4 index loads) + relu, GAT linear,
// attention dots, global max of a_src.
__global__ void k_layer1(const float* __restrict__ Wg, const float* __restrict__ b1,
                         const float* __restrict__ attS, const float* __restrict__ attD, int n) {
    __shared__ float sWg[32 * 64];
    __shared__ unsigned smax[2];
    int tid = threadIdx.x;
    for (int i = tid; i < 2048; i += blockDim.x) sWg[i] = Wg[i];
    if (tid < 2) smax[tid] = 0u;
    __syncthreads();

    int node = (blockIdx.x * blockDim.x + tid) >> 5;
    int lane = tid & 31;
    if (node < n) {
        float a0 = __half2float(g_hs[node * 32 + lane]);   // self loop
        float a1 = 0.f, a2 = 0.f, a3 = 0.f;
        int off = g_off[node], end = off + g_deg[node];
        int j = off;
        for (; j + 3 < end; j += 4) {
            int4 e01 = *(const int4*)&g_edge[j];       // (r0,c0,r1,c1)
            int4 e23 = *(const int4*)&g_edge[j + 2];
            a0 += __half2float(g_hs[e01.x * 32 + lane]);
            a1 += __half2float(g_hs[e01.z * 32 + lane]);
            a2 += __half2float(g_hs[e23.x * 32 + lane]);
            a3 += __half2float(g_hs[e23.z * 32 + lane]);
        }
        for (; j < end; j++) a0 += __half2float(g_hs[g_edge[j].x * 32 + lane]);
        float acc = (a0 + a1) + (a2 + a3);

        float h1 = fmaxf(fmaf(g_dinv[node], acc, b1[lane]), 0.f);

        float o0 = 0.f, o1 = 0.f;
#pragma unroll
        for (int i = 0; i < 32; i++) {
            float hv = __shfl_sync(0xffffffffu, h1, i);
            o0 = fmaf(hv, sWg[i * 64 + lane], o0);
            o1 = fmaf(hv, sWg[i * 64 + 32 + lane], o1);
        }
        g_hgh[node * 64 + lane]      = __float2half(o0);
        g_hgh[node * 64 + 32 + lane] = __float2half(o1);

        float as0 = o0 * attS[lane];
        float as1 = o1 * attS[32 + lane];
        float ad0 = o0 * attD[lane];
        float ad1 = o1 * attD[32 + lane];
#pragma unroll
        for (int o = 16; o; o >>= 1) {
            as0 += __shfl_down_sync(0xffffffffu, as0, o);
            as1 += __shfl_down_sync(0xffffffffu, as1, o);
            ad0 += __shfl_down_sync(0xffffffffu, ad0, o);
            ad1 += __shfl_down_sync(0xffffffffu, ad1, o);
        }
        if (lane == 0) {
            g_asrc[node * 2]     = as0;
            g_asrc[node * 2 + 1] = as1;
            g_adst[node * 2]     = ad0;
            g_adst[node * 2 + 1] = ad1;
            atomicMax(&smax[0], encf(as0));
            atomicMax(&smax[1], encf(as1));
        }
    }
    __syncthreads();
    if (tid < 2) atomicMax(&g_gmaxe[tid], smax[tid]);
}

// edge-parallel: softmax numerators (both heads), coalesced over padded slots.
__global__ void k_edgeex() {
    int j = blockIdx.x * blockDim.x + threadIdx.x;
    if (j >= g_total) return;
    int2 e = g_edge[j];
    float2 as = *(const float2*)&g_asrc[2 * e.x];
    float2 ad = *(const float2*)&g_adst[2 * e.y];
    float m0 = lrelu(decf(g_gmaxe[0]) + ad.x);
    float m1 = lrelu(decf(g_gmaxe[1]) + ad.y);
    float2 ex;
    ex.x = __expf(lrelu(as.x + ad.x) - m0);
    ex.y = __expf(lrelu(as.y + ad.y) - m1);
    *(float2*)&g_ex[2 * j] = ex;
}

// warp per node: lanes 0-15 head0 (channel pairs), lanes 16-31 head1.
__global__ void k_gat(const float* __restrict__ gat_b, const float* __restrict__ W2, int n) {
    int tid = threadIdx.x;
    int node = (blockIdx.x * blockDim.x + tid) >> 5;
    int lane = tid & 31;
    if (node >= n) return;
    bool head1 = lane >= 16;
    int ch = (lane & 15) * 2;
    const unsigned* hgu = (const unsigned*)g_hgh;

    float2 ad = *(const float2*)&g_adst[2 * node];
    float2 as = *(const float2*)&g_asrc[2 * node];
    float m   = head1 ? lrelu(decf(g_gmaxe[1]) + ad.y) : lrelu(decf(g_gmaxe[0]) + ad.x);
    float es  = head1 ? lrelu(as.y + ad.y) : lrelu(as.x + ad.x);
    float exs = __expf(es - m);

    unsigned hv = hgu[node * 32 + lane];
    float2 hf = __half22float2(*(const __half2*)&hv);
    float sA = exs, sB = 0.f;
    float accx = exs * hf.x, accy = exs * hf.y;
    float acc2x = 0.f, acc2y = 0.f;

    int off = g_off[node], end = off + g_deg[node];
    int j = off;
    for (; j + 1 < end; j += 2) {
        int4 e01 = *(const int4*)&g_edge[j];          // r0,c0,r1,c1
        float4 exv = *(const float4*)&g_ex[2 * j];    // ex0(h0,h1), ex1(h0,h1)
        unsigned h0 = hgu[e01.x * 32 + lane];
        unsigned h1 = hgu[e01.z * 32 + lane];
        float w0 = head1 ? exv.y : exv.x;
        float w1 = head1 ? exv.w : exv.z;
        float2 f0 = __half22float2(*(const __half2*)&h0);
        float2 f1 = __half22float2(*(const __half2*)&h1);
        accx  = fmaf(w0, f0.x, accx);
        accy  = fmaf(w0, f0.y, accy);
        acc2x = fmaf(w1, f1.x, acc2x);
        acc2y = fmaf(w1, f1.y, acc2y);
        sA += w0; sB += w1;
    }
    if (j < end) {
        int2 e0 = g_edge[j];
        float2 exv = *(const float2*)&g_ex[2 * j];
        unsigned h0 = hgu[e0.x * 32 + lane];
        float w0 = head1 ? exv.y : exv.x;
        float2 f0 = __half22float2(*(const __half2*)&h0);
        accx = fmaf(w0, f0.x, accx);
        accy = fmaf(w0, f0.y, accy);
        sA += w0;
    }
    float s = sA + sB;
    float vx = (accx + acc2x) / s;
    float vy = (accy + acc2y) / s;

    float ox = __shfl_down_sync(0xffffffffu, vx, 16);
    float oy = __shfl_down_sync(0xffffffffu, vy, 16);
    float c0 = fmaxf(fmaf(0.5f, vx + ox, gat_b[ch]),     0.f);
    float c1 = fmaxf(fmaf(0.5f, vy + oy, gat_b[ch + 1]), 0.f);
    float zi = fmaf(c0, W2[ch], c1 * W2[ch + 1]);
#pragma unroll
    for (int o = 8; o; o >>= 1)
        zi += __shfl_down_sync(0xffffffffu, zi, o);
    if (lane == 0) g_z[node] = g_dinv[node] * zi;
}

__global__ void k_gcn2(float* __restrict__ out, const float* __restrict__ b2, int n) {
    int tid = threadIdx.x;
    int node = (blockIdx.x * blockDim.x + tid) >> 5;
    int lane = tid & 31;
    if (node >= n) return;
    float s = (lane == 0) ? g_z[node] : 0.f;
    int off = g_off[node], end = off + g_deg[node];
    for (int j = off + lane; j < end; j += 32)
        s += g_z[g_edge[j].x];
#pragma unroll
    for (int o = 16; o; o >>= 1)
        s += __shfl_down_sync(0xffffffffu, s, o);
    if (lane == 0) out[node] = fmaf(g_dinv[node], s, b2[0]);
}

// ---------------- launch ----------------
extern "C" void kernel_launch(void* const* d_in, const int* in_sizes, int n_in,
                              void* d_out, int out_size) {
    const float* x    = (const float*)d_in[0];
    const void*  ei   = d_in[1];
    const float* W1   = (const float*)d_in[2];
    const float* b1   = (const float*)d_in[3];
    const float* Wg   = (const float*)d_in[4];
    const float* attS = (const float*)d_in[5];
    const float* attD = (const float*)d_in[6];
    const float* gb   = (const float*)d_in[7];
    const float* W2   = (const float*)d_in[8];
    const float* b2   = (const float*)d_in[9];
    float* out = (float*)d_out;

    int n = in_sizes[0] / 2;
    int E = in_sizes[1] / 2;
    int EP = E + 3 * n;          // padded CSR capacity for this instance
    const int T = 256;
    int nb = (n + 1023) / 1024;

    k_zero<<<(EP + T - 1) / T, T>>>((const int*)ei, n, EP);
    k_degcount<<<(E + T - 1) / T, T>>>(ei, E);
    k_scan1<<<nb, 1024>>>(n);
    k_scan2<<<1, 32>>>(nb);
    k_scan3<<<nb, 1024>>>(n);
    k_fill<<<(E + T - 1) / T, T>>>(ei, E);
    k_node1<<<(n * 32 + T - 1) / T, T>>>(x, W1, n);
    k_layer1<<<(n * 32 + T - 1) / T, T>>>(Wg, b1, attS, attD, n);
    k_edgeex<<<(EP + T - 1) / T, T>>>();
    k_gat<<<(n * 32 + T - 1) / T, T>>>(gb, W2, n);
    k_gcn2<<<(n * 32 + T - 1) / T, T>>>(out, b2, n);
}

// round 6
// speedup vs baseline: 1.2002x; 1.0011x over previous
#include <cuda_runtime.h>
#include <cuda_fp16.h>
#include <cuda_bf16.h>

// RoadGNN: GCN(2->32) -> ReLU -> GAT(32->2x32, mean heads) -> ReLU -> GCN(32->1)
// CSR gather (padded-4 segments, src-only), fp16 feature gathers,
// GAT softmax weights computed lane-parallel inside the gather kernel.

#define MAXN 100000
#define MAXE 1600000
#define MAXEP (MAXE + 3 * MAXN + 32)   // padded CSR capacity + chunk-read margin

// ---------------- scratch ----------------
__device__ int      g_deg[MAXN];
__device__ int      g_off[MAXN];      // padded exclusive offsets (mult of 4)
__device__ int      g_cur[MAXN];
__device__ __align__(16) int g_csr[MAXEP];   // src ids grouped by dst
__device__ int      g_bsum[128];
__device__ float    g_dinv[MAXN];
__device__ __half   g_hs[MAXN * 32];  // dinv[n]*(x@W1)[n], fp16
__device__ __half   g_hgh[MAXN * 64]; // GAT linear out fp16 (h0|h1)
__device__ float    g_asrc[MAXN * 2];
__device__ float    g_adst[MAXN * 2];
__device__ unsigned g_gmaxe[2];
__device__ float    g_z[MAXN];
__device__ int      g_is64;

// ---------------- helpers ----------------
__device__ __forceinline__ float lrelu(float v) { return v > 0.f ? v : 0.2f * v; }
__device__ __forceinline__ unsigned encf(float f) {
    unsigned u = __float_as_uint(f);
    return (u & 0x80000000u) ? ~u : (u | 0x80000000u);
}
__device__ __forceinline__ float decf(unsigned u) {
    return __uint_as_float((u & 0x80000000u) ? (u & 0x7fffffffu) : ~u);
}
__device__ __forceinline__ void load_edge(const void* ei, int e, int E, int& r, int& c) {
    if (g_is64) {
        const long long* p = (const long long*)ei;
        r = (int)p[e]; c = (int)p[E + e];
    } else {
        const int* p = (const int*)ei;
        r = p[e]; c = p[E + e];
    }
}

// ---------------- kernels ----------------
__global__ void k_zero(const int* __restrict__ ei32, int n) {
    int gid = blockIdx.x * blockDim.x + threadIdx.x;
    if (gid < n) { g_deg[gid] = 0; g_cur[gid] = 0; }
    if (gid == 0) {
        int is64 = 1;
        for (int i = 0; i < 64; i++)
            if (ei32[2 * i + 1] != 0) { is64 = 0; break; }
        g_is64 = is64;
        g_gmaxe[0] = 0u; g_gmaxe[1] = 0u;
    }
}

__global__ void k_degcount(const void* __restrict__ ei, int E) {
    int e = blockIdx.x * blockDim.x + threadIdx.x;
    if (e >= E) return;
    int c;
    if (g_is64) c = (int)((const long long*)ei)[E + e];
    else        c = ((const int*)ei)[E + e];
    atomicAdd(&g_deg[c], 1);
}

__global__ void k_scan1(int n) {
    __shared__ int sh[1024];
    int tid = threadIdx.x;
    int i = blockIdx.x * 1024 + tid;
    int v = (i < n) ? ((g_deg[i] + 3) & ~3) : 0;
    sh[tid] = v;
    __syncthreads();
#pragma unroll
    for (int d = 1; d < 1024; d <<= 1) {
        int t = (tid >= d) ? sh[tid - d] : 0;
        __syncthreads();
        sh[tid] += t;
        __syncthreads();
    }
    if (i < n) g_off[i] = sh[tid] - v;
    if (tid == 1023) g_bsum[blockIdx.x] = sh[1023];
}

__global__ void k_scan2(int nb) {
    int lane = threadIdx.x;
    int carry = 0;
    for (int base = 0; base < nb; base += 32) {
        int idx = base + lane;
        int v = (idx < nb) ? g_bsum[idx] : 0;
        int orig = v;
#pragma unroll
        for (int o = 1; o < 32; o <<= 1) {
            int t = __shfl_up_sync(0xffffffffu, v, o);
            if (lane >= o) v += t;
        }
        int tot = __shfl_sync(0xffffffffu, v, 31);
        if (idx < nb) g_bsum[idx] = v - orig + carry;
        carry += tot;
    }
}

__global__ void k_scan3(int n) {
    int i = blockIdx.x * 1024 + threadIdx.x;
    if (i < n) g_off[i] += g_bsum[blockIdx.x];
}

__global__ void k_fill(const void* __restrict__ ei, int E) {
    int e = blockIdx.x * blockDim.x + threadIdx.x;
    if (e >= E) return;
    int r, c; load_edge(ei, e, E, r, c);
    int pos = g_off[c] + atomicAdd(&g_cur[c], 1);
    g_csr[pos] = r;
}

__global__ void k_node1(const float* __restrict__ x, const float* __restrict__ W1, int n) {
    int gid = blockIdx.x * blockDim.x + threadIdx.x;
    if (gid >= n * 32) return;
    int node = gid >> 5, k = gid & 31;
    float d = rsqrtf((float)(g_deg[node] + 1));
    if (k == 0) g_dinv[node] = d;
    float hp = fmaf(x[2 * node], W1[k], x[2 * node + 1] * W1[32 + k]);
    g_hs[gid] = __float2half(d * hp);
}

// warp per node: GCN1 gather (fp16, int4 index loads: 4 edges/16B) + relu,
// GAT linear, attention dots, global max of a_src.
__global__ void k_layer1(const float* __restrict__ Wg, const float* __restrict__ b1,
                         const float* __restrict__ attS, const float* __restrict__ attD, int n) {
    __shared__ float sWg[32 * 64];
    __shared__ unsigned smax[2];
    int tid = threadIdx.x;
    for (int i = tid; i < 2048; i += blockDim.x) sWg[i] = Wg[i];
    if (tid < 2) smax[tid] = 0u;
    __syncthreads();

    int node = (blockIdx.x * blockDim.x + tid) >> 5;
    int lane = tid & 31;
    if (node < n) {
        float a0 = __half2float(g_hs[node * 32 + lane]);   // self loop
        float a1 = 0.f, a2 = 0.f, a3 = 0.f;
        int off = g_off[node], end = off + g_deg[node];
        int j = off;
        for (; j + 3 < end; j += 4) {
            int4 e4 = *(const int4*)&g_csr[j];
            a0 += __half2float(g_hs[e4.x * 32 + lane]);
            a1 += __half2float(g_hs[e4.y * 32 + lane]);
            a2 += __half2float(g_hs[e4.z * 32 + lane]);
            a3 += __half2float(g_hs[e4.w * 32 + lane]);
        }
        for (; j < end; j++) a0 += __half2float(g_hs[g_csr[j] * 32 + lane]);
        float acc = (a0 + a1) + (a2 + a3);

        float h1 = fmaxf(fmaf(g_dinv[node], acc, b1[lane]), 0.f);

        float o0 = 0.f, o1 = 0.f;
#pragma unroll
        for (int i = 0; i < 32; i++) {
            float hv = __shfl_sync(0xffffffffu, h1, i);
            o0 = fmaf(hv, sWg[i * 64 + lane], o0);
            o1 = fmaf(hv, sWg[i * 64 + 32 + lane], o1);
        }
        g_hgh[node * 64 + lane]      = __float2half(o0);
        g_hgh[node * 64 + 32 + lane] = __float2half(o1);

        float as0 = o0 * attS[lane];
        float as1 = o1 * attS[32 + lane];
        float ad0 = o0 * attD[lane];
        float ad1 = o1 * attD[32 + lane];
#pragma unroll
        for (int o = 16; o; o >>= 1) {
            as0 += __shfl_down_sync(0xffffffffu, as0, o);
            as1 += __shfl_down_sync(0xffffffffu, as1, o);
            ad0 += __shfl_down_sync(0xffffffffu, ad0, o);
            ad1 += __shfl_down_sync(0xffffffffu, ad1, o);
        }
        if (lane == 0) {
            g_asrc[node * 2]     = as0;
            g_asrc[node * 2 + 1] = as1;
            g_adst[node * 2]     = ad0;
            g_adst[node * 2 + 1] = ad1;
            atomicMax(&smax[0], encf(as0));
            atomicMax(&smax[1], encf(as1));
        }
    }
    __syncthreads();
    if (tid < 2) atomicMax(&g_gmaxe[tid], smax[tid]);
}

// warp per node: chunked. Phase A (lane-parallel): load 32 csr indices,
// gather a_src, compute both heads' exp-weights. Phase B: shfl-broadcast
// (r, w) per edge, gather 128B fp16 hg, accumulate. Lanes 0-15 head0, 16-31 head1.
__global__ void k_gat(const float* __restrict__ gat_b, const float* __restrict__ W2, int n) {
    int tid = threadIdx.x;
    int node = (blockIdx.x * blockDim.x + tid) >> 5;
    int lane = tid & 31;
    if (node >= n) return;
    bool head1 = lane >= 16;
    int ch = (lane & 15) * 2;
    const unsigned* hgu = (const unsigned*)g_hgh;

    float2 ad = *(const float2*)&g_adst[2 * node];
    float2 as = *(const float2*)&g_asrc[2 * node];
    float m0 = lrelu(decf(g_gmaxe[0]) + ad.x);
    float m1 = lrelu(decf(g_gmaxe[1]) + ad.y);
    float m  = head1 ? m1 : m0;
    float es = head1 ? lrelu(as.y + ad.y) : lrelu(as.x + ad.x);
    float exs = __expf(es - m);

    unsigned hv = hgu[node * 32 + lane];
    float2 hf = __half22float2(*(const __half2*)&hv);
    float s = exs;
    float accx = exs * hf.x, accy = exs * hf.y;

    int off = g_off[node], deg = g_deg[node];
    for (int base = 0; base < deg; base += 32) {
        int cnt = min(32, deg - base);
        int r_l = g_csr[off + base + ((lane < cnt) ? lane : 0)];
        float2 asl = *(const float2*)&g_asrc[2 * r_l];
        float exA = __expf(lrelu(asl.x + ad.x) - m0);
        float exB = __expf(lrelu(asl.y + ad.y) - m1);
#pragma unroll 4
        for (int k = 0; k < cnt; k++) {
            int r = __shfl_sync(0xffffffffu, r_l, k);
            float w0 = __shfl_sync(0xffffffffu, exA, k);
            float w1 = __shfl_sync(0xffffffffu, exB, k);
            float w = head1 ? w1 : w0;
            unsigned h = hgu[r * 32 + lane];
            float2 f = __half22float2(*(const __half2*)&h);
            accx = fmaf(w, f.x, accx);
            accy = fmaf(w, f.y, accy);
            s += w;
        }
    }
    float vx = accx / s;
    float vy = accy / s;

    float ox = __shfl_down_sync(0xffffffffu, vx, 16);
    float oy = __shfl_down_sync(0xffffffffu, vy, 16);
    float c0 = fmaxf(fmaf(0.5f, vx + ox, gat_b[ch]),     0.f);
    float c1 = fmaxf(fmaf(0.5f, vy + oy, gat_b[ch + 1]), 0.f);
    float zi = fmaf(c0, W2[ch], c1 * W2[ch + 1]);
#pragma unroll
    for (int o = 8; o; o >>= 1)
        zi += __shfl_down_sync(0xffffffffu, zi, o);
    if (lane == 0) g_z[node] = g_dinv[node] * zi;
}

__global__ void k_gcn2(float* __restrict__ out, const float* __restrict__ b2, int n) {
    int tid = threadIdx.x;
    int node = (blockIdx.x * blockDim.x + tid) >> 5;
    int lane = tid & 31;
    if (node >= n) return;
    float s = (lane == 0) ? g_z[node] : 0.f;
    int off = g_off[node], end = off + g_deg[node];
    for (int j = off + lane; j < end; j += 32)
        s += g_z[g_csr[j]];
#pragma unroll
    for (int o = 16; o; o >>= 1)
        s += __shfl_down_sync(0xffffffffu, s, o);
    if (lane == 0) out[node] = fmaf(g_dinv[node], s, b2[0]);
}

// ---------------- launch ----------------
extern "C" void kernel_launch(void* const* d_in, const int* in_sizes, int n_in,
                              void* d_out, int out_size) {
    const float* x    = (const float*)d_in[0];
    const void*  ei   = d_in[1];
    const float* W1   = (const float*)d_in[2];
    const float* b1   = (const float*)d_in[3];
    const float* Wg   = (const float*)d_in[4];
    const float* attS = (const float*)d_in[5];
    const float* attD = (const float*)d_in[6];
    const float* gb   = (const float*)d_in[7];
    const float* W2   = (const float*)d_in[8];
    const float* b2   = (const float*)d_in[9];
    float* out = (float*)d_out;

    int n = in_sizes[0] / 2;
    int E = in_sizes[1] / 2;
    const int T = 256;
    int nb = (n + 1023) / 1024;

    k_zero<<<(n + T - 1) / T, T>>>((const int*)ei, n);
    k_degcount<<<(E + T - 1) / T, T>>>(ei, E);
    k_scan1<<<nb, 1024>>>(n);
    k_scan2<<<1, 32>>>(nb);
    k_scan3<<<nb, 1024>>>(n);
    k_fill<<<(E + T - 1) / T, T>>>(ei, E);
    k_node1<<<(n * 32 + T - 1) / T, T>>>(x, W1, n);
    k_layer1<<<(n * 32 + T - 1) / T, T>>>(Wg, b1, attS, attD, n);
    k_gat<<<(n * 32 + T - 1) / T, T>>>(gb, W2, n);
    k_gcn2<<<(n * 32 + T - 1) / T, T>>>(out, b2, n);
}

// round 7
// speedup vs baseline: 1.2121x; 1.0099x over previous
#include <cuda_runtime.h>
#include <cuda_fp16.h>
#include <cuda_bf16.h>

// RoadGNN: GCN(2->32) -> ReLU -> GAT(32->2x32, mean heads) -> ReLU -> GCN(32->1)
// CSR gather, fp16 feature gathers, inline GAT softmax, 8 launches.
// Scratch counters are reset by the LAST kernel for the next call
// (module load gives the first call zeros), so no zeroing pass is needed.

#define MAXN 100000
#define MAXE 1600000
#define MAXEP (MAXE + 3 * MAXN + 32)

// ---------------- scratch ----------------
__device__ int      g_deg[MAXN];        // zeroed by k_gcn2 tail each call
__device__ int      g_off[MAXN];
__device__ int      g_cur[MAXN];        // zeroed by k_gcn2 tail each call
__device__ __align__(16) int g_csr[MAXEP];
__device__ int      g_bsum[128];
__device__ float    g_dinv[MAXN];
__device__ __half   g_hs[MAXN * 32];
__device__ __half   g_hgh[MAXN * 64];
__device__ float    g_asrc[MAXN * 2];
__device__ float    g_adst[MAXN * 2];
__device__ unsigned g_gmaxe[2];         // zeroed by k_gcn2 tail each call
__device__ float    g_z[MAXN];

// ---------------- helpers ----------------
__device__ __forceinline__ float lrelu(float v) { return v > 0.f ? v : 0.2f * v; }
__device__ __forceinline__ unsigned encf(float f) {
    unsigned u = __float_as_uint(f);
    return (u & 0x80000000u) ? ~u : (u | 0x80000000u);
}
__device__ __forceinline__ float decf(unsigned u) {
    return __uint_as_float((u & 0x80000000u) ? (u & 0x7fffffffu) : ~u);
}

// per-block edge-index dtype detect (int64 nonneg < 2^31 => odd int32 words 0)
__device__ __forceinline__ int block_is64(const int* ei32, int* sh) {
    if (threadIdx.x == 0) {
        int is64 = 1;
        for (int i = 0; i < 64; i++)
            if (ei32[2 * i + 1] != 0) { is64 = 0; break; }
        *sh = is64;
    }
    __syncthreads();
    return *sh;
}

// ---------------- kernels ----------------

// launch 1: in-degree count (reads only col half)
__global__ void k_degcount(const void* __restrict__ ei, int E) {
    __shared__ int sh;
    int is64 = block_is64((const int*)ei, &sh);
    int e = blockIdx.x * blockDim.x + threadIdx.x;
    if (e >= E) return;
    int c;
    if (is64) c = (int)((const long long*)ei)[E + e];
    else      c = ((const int*)ei)[E + e];
    atomicAdd(&g_deg[c], 1);
}

// launch 2: block-local scan of 4-padded degrees
__global__ void k_scan1(int n) {
    __shared__ int sh[1024];
    int tid = threadIdx.x;
    int i = blockIdx.x * 1024 + tid;
    int v = (i < n) ? ((g_deg[i] + 3) & ~3) : 0;
    sh[tid] = v;
    __syncthreads();
#pragma unroll
    for (int d = 1; d < 1024; d <<= 1) {
        int t = (tid >= d) ? sh[tid - d] : 0;
        __syncthreads();
        sh[tid] += t;
        __syncthreads();
    }
    if (i < n) g_off[i] = sh[tid] - v;
    if (tid == 1023) g_bsum[blockIdx.x] = sh[1023];
}

// launch 3: each block sums bsum[0..blockIdx) itself, then offsets its slice
__global__ void k_scan23(int n, int nb) {
    __shared__ int spre;
    int tid = threadIdx.x;
    if (tid < 32) {
        int p = 0;
        for (int k = tid; k < blockIdx.x; k += 32) p += g_bsum[k];
#pragma unroll
        for (int o = 16; o; o >>= 1) p += __shfl_down_sync(0xffffffffu, p, o);
        if (tid == 0) spre = p;
    }
    __syncthreads();
    int i = blockIdx.x * 1024 + tid;
    if (i < n) g_off[i] += spre;
}

// launch 4 (ncu capture slot): CSR bucket fill
__global__ void k_fill(const void* __restrict__ ei, int E) {
    __shared__ int sh;
    int is64 = block_is64((const int*)ei, &sh);
    int e = blockIdx.x * blockDim.x + threadIdx.x;
    if (e >= E) return;
    int r, c;
    if (is64) {
        const long long* p = (const long long*)ei;
        r = (int)p[e]; c = (int)p[E + e];
    } else {
        const int* p = (const int*)ei;
        r = p[e]; c = p[E + e];
    }
    int pos = g_off[c] + atomicAdd(&g_cur[c], 1);
    g_csr[pos] = r;
}

// launch 5: dinv + hs = dinv*(x@W1) in fp16
__global__ void k_node1(const float* __restrict__ x, const float* __restrict__ W1, int n) {
    int gid = blockIdx.x * blockDim.x + threadIdx.x;
    if (gid >= n * 32) return;
    int node = gid >> 5, k = gid & 31;
    float d = rsqrtf((float)(g_deg[node] + 1));
    if (k == 0) g_dinv[node] = d;
    float hp = fmaf(x[2 * node], W1[k], x[2 * node + 1] * W1[32 + k]);
    g_hs[gid] = __float2half(d * hp);
}

// launch 6: warp/node: GCN1 gather + relu, GAT linear, attention dots, global max
__global__ void k_layer1(const float* __restrict__ Wg, const float* __restrict__ b1,
                         const float* __restrict__ attS, const float* __restrict__ attD, int n) {
    __shared__ float sWg[32 * 64];
    __shared__ unsigned smax[2];
    int tid = threadIdx.x;
    for (int i = tid; i < 2048; i += blockDim.x) sWg[i] = Wg[i];
    if (tid < 2) smax[tid] = 0u;
    __syncthreads();

    int node = (blockIdx.x * blockDim.x + tid) >> 5;
    int lane = tid & 31;
    if (node < n) {
        float a0 = __half2float(g_hs[node * 32 + lane]);
        float a1 = 0.f, a2 = 0.f, a3 = 0.f;
        int off = g_off[node], end = off + g_deg[node];
        int j = off;
        for (; j + 3 < end; j += 4) {
            int4 e4 = *(const int4*)&g_csr[j];
            a0 += __half2float(g_hs[e4.x * 32 + lane]);
            a1 += __half2float(g_hs[e4.y * 32 + lane]);
            a2 += __half2float(g_hs[e4.z * 32 + lane]);
            a3 += __half2float(g_hs[e4.w * 32 + lane]);
        }
        for (; j < end; j++) a0 += __half2float(g_hs[g_csr[j] * 32 + lane]);
        float acc = (a0 + a1) + (a2 + a3);

        float h1 = fmaxf(fmaf(g_dinv[node], acc, b1[lane]), 0.f);

        float o0 = 0.f, o1 = 0.f;
#pragma unroll
        for (int i = 0; i < 32; i++) {
            float hv = __shfl_sync(0xffffffffu, h1, i);
            o0 = fmaf(hv, sWg[i * 64 + lane], o0);
            o1 = fmaf(hv, sWg[i * 64 + 32 + lane], o1);
        }
        g_hgh[node * 64 + lane]      = __float2half(o0);
        g_hgh[node * 64 + 32 + lane] = __float2half(o1);

        float as0 = o0 * attS[lane];
        float as1 = o1 * attS[32 + lane];
        float ad0 = o0 * attD[lane];
        float ad1 = o1 * attD[32 + lane];
#pragma unroll
        for (int o = 16; o; o >>= 1) {
            as0 += __shfl_down_sync(0xffffffffu, as0, o);
            as1 += __shfl_down_sync(0xffffffffu, as1, o);
            ad0 += __shfl_down_sync(0xffffffffu, ad0, o);
            ad1 += __shfl_down_sync(0xffffffffu, ad1, o);
        }
        if (lane == 0) {
            g_asrc[node * 2]     = as0;
            g_asrc[node * 2 + 1] = as1;
            g_adst[node * 2]     = ad0;
            g_adst[node * 2 + 1] = ad1;
            atomicMax(&smax[0], encf(as0));
            atomicMax(&smax[1], encf(as1));
        }
    }
    __syncthreads();
    if (tid < 2) atomicMax(&g_gmaxe[tid], smax[tid]);
}

// launch 7: warp/node GAT: lane-parallel softmax weights, shfl-broadcast aggregate
__global__ void k_gat(const float* __restrict__ gat_b, const float* __restrict__ W2, int n) {
    int tid = threadIdx.x;
    int node = (blockIdx.x * blockDim.x + tid) >> 5;
    int lane = tid & 31;
    if (node >= n) return;
    bool head1 = lane >= 16;
    int ch = (lane & 15) * 2;
    const unsigned* hgu = (const unsigned*)g_hgh;

    float2 ad = *(const float2*)&g_adst[2 * node];
    float2 as = *(const float2*)&g_asrc[2 * node];
    float m0 = lrelu(decf(g_gmaxe[0]) + ad.x);
    float m1 = lrelu(decf(g_gmaxe[1]) + ad.y);
    float m  = head1 ? m1 : m0;
    float es = head1 ? lrelu(as.y + ad.y) : lrelu(as.x + ad.x);
    float exs = __expf(es - m);

    unsigned hv = hgu[node * 32 + lane];
    float2 hf = __half22float2(*(const __half2*)&hv);
    float s = exs;
    float accx = exs * hf.x, accy = exs * hf.y;

    int off = g_off[node], deg = g_deg[node];
    for (int base = 0; base < deg; base += 32) {
        int cnt = min(32, deg - base);
        int r_l = g_csr[off + base + ((lane < cnt) ? lane : 0)];
        float2 asl = *(const float2*)&g_asrc[2 * r_l];
        float exA = __expf(lrelu(asl.x + ad.x) - m0);
        float exB = __expf(lrelu(asl.y + ad.y) - m1);
#pragma unroll 4
        for (int k = 0; k < cnt; k++) {
            int r = __shfl_sync(0xffffffffu, r_l, k);
            float w0 = __shfl_sync(0xffffffffu, exA, k);
            float w1 = __shfl_sync(0xffffffffu, exB, k);
            float w = head1 ? w1 : w0;
            unsigned h = hgu[r * 32 + lane];
            float2 f = __half22float2(*(const __half2*)&h);
            accx = fmaf(w, f.x, accx);
            accy = fmaf(w, f.y, accy);
            s += w;
        }
    }
    float vx = accx / s;
    float vy = accy / s;

    float ox = __shfl_down_sync(0xffffffffu, vx, 16);
    float oy = __shfl_down_sync(0xffffffffu, vy, 16);
    float c0 = fmaxf(fmaf(0.5f, vx + ox, gat_b[ch]),     0.f);
    float c1 = fmaxf(fmaf(0.5f, vy + oy, gat_b[ch + 1]), 0.f);
    float zi = fmaf(c0, W2[ch], c1 * W2[ch + 1]);
#pragma unroll
    for (int o = 8; o; o >>= 1)
        zi += __shfl_down_sync(0xffffffffu, zi, o);
    if (lane == 0) g_z[node] = g_dinv[node] * zi;
}

// launch 8: warp/node GCN2 gather + output; tail-resets counters for next call
__global__ void k_gcn2(float* __restrict__ out, const float* __restrict__ b2, int n) {
    int tid = threadIdx.x;
    int gid = blockIdx.x * blockDim.x + tid;
    int node = gid >> 5;
    int lane = tid & 31;
    if (node >= n) return;
    float s = (lane == 0) ? g_z[node] : 0.f;
    int off = g_off[node], end = off + g_deg[node];
    for (int j = off + lane; j < end; j += 32)
        s += g_z[g_csr[j]];
#pragma unroll
    for (int o = 16; o; o >>= 1)
        s += __shfl_down_sync(0xffffffffu, s, o);
    if (lane == 0) {
        out[node] = fmaf(g_dinv[node], s, b2[0]);
        g_deg[node] = 0;          // reset for next call
        g_cur[node] = 0;
        if (node == 0) { g_gmaxe[0] = 0u; g_gmaxe[1] = 0u; }
    }
}

// ---------------- launch ----------------
extern "C" void kernel_launch(void* const* d_in, const int* in_sizes, int n_in,
                              void* d_out, int out_size) {
    const float* x    = (const float*)d_in[0];
    const void*  ei   = d_in[1];
    const float* W1   = (const float*)d_in[2];
    const float* b1   = (const float*)d_in[3];
    const float* Wg   = (const float*)d_in[4];
    const float* attS = (const float*)d_in[5];
    const float* attD = (const float*)d_in[6];
    const float* gb   = (const float*)d_in[7];
    const float* W2   = (const float*)d_in[8];
    const float* b2   = (const float*)d_in[9];
    float* out = (float*)d_out;

    int n = in_sizes[0] / 2;
    int E = in_sizes[1] / 2;
    const int T = 256;
    int nb = (n + 1023) / 1024;

    k_degcount<<<(E + T - 1) / T, T>>>(ei, E);
    k_scan1<<<nb, 1024>>>(n);
    k_scan23<<<nb, 1024>>>(n, nb);
    k_fill<<<(E + T - 1) / T, T>>>(ei, E);
    k_node1<<<(n * 32 + T - 1) / T, T>>>(x, W1, n);
    k_layer1<<<(n * 32 + T - 1) / T, T>>>(Wg, b1, attS, attD, n);
    k_gat<<<(n * 32 + T - 1) / T, T>>>(gb, W2, n);
    k_gcn2<<<(n * 32 + T - 1) / T, T>>>(out, b2, n);
}

// round 8
// speedup vs baseline: 1.2869x; 1.0618x over previous
#include <cuda_runtime.h>
#include <cuda_fp16.h>
#include <cuda_bf16.h>

// RoadGNN: GCN(2->32) -> ReLU -> GAT(32->2x32, mean heads) -> ReLU -> GCN(32->1)
// GCN1 aggregated in INPUT space (2 floats/edge, lane-parallel) via linearity;
// GAT gather fp16; CSR build with counting sort; counters reset by last kernel.

#define MAXN 100000
#define MAXE 1600000
#define MAXEP (MAXE + 3 * MAXN + 32)

// ---------------- scratch ----------------
__device__ int      g_deg[MAXN];        // zeroed by k_gcn2 tail each call
__device__ int      g_off[MAXN];
__device__ int      g_cur[MAXN];        // zeroed by k_gcn2 tail each call
__device__ __align__(16) int g_csr[MAXEP];
__device__ int      g_bsum[128];
__device__ float    g_dinv[MAXN];
__device__ __align__(8) float2 g_xt[MAXN];   // dinv[n] * x[n]  (2 features)
__device__ __half   g_hgh[MAXN * 64];        // GAT linear out fp16 (h0|h1)
__device__ float    g_asrc[MAXN * 2];
__device__ float    g_adst[MAXN * 2];
__device__ unsigned g_gmaxe[2];         // zeroed by k_gcn2 tail each call
__device__ float    g_z[MAXN];

// ---------------- helpers ----------------
__device__ __forceinline__ float lrelu(float v) { return v > 0.f ? v : 0.2f * v; }
__device__ __forceinline__ unsigned encf(float f) {
    unsigned u = __float_as_uint(f);
    return (u & 0x80000000u) ? ~u : (u | 0x80000000u);
}
__device__ __forceinline__ float decf(unsigned u) {
    return __uint_as_float((u & 0x80000000u) ? (u & 0x7fffffffu) : ~u);
}
__device__ __forceinline__ int block_is64(const int* ei32, int* sh) {
    if (threadIdx.x == 0) {
        int is64 = 1;
        for (int i = 0; i < 64; i++)
            if (ei32[2 * i + 1] != 0) { is64 = 0; break; }
        *sh = is64;
    }
    __syncthreads();
    return *sh;
}

// ---------------- kernels ----------------

// launch 1: in-degree count (col half only)
__global__ void k_degcount(const void* __restrict__ ei, int E) {
    __shared__ int sh;
    int is64 = block_is64((const int*)ei, &sh);
    int e = blockIdx.x * blockDim.x + threadIdx.x;
    if (e >= E) return;
    int c;
    if (is64) c = (int)((const long long*)ei)[E + e];
    else      c = ((const int*)ei)[E + e];
    atomicAdd(&g_deg[c], 1);
}

// launch 2: block-local scan of 4-padded degrees
__global__ void k_scan1(int n) {
    __shared__ int sh[1024];
    int tid = threadIdx.x;
    int i = blockIdx.x * 1024 + tid;
    int v = (i < n) ? ((g_deg[i] + 3) & ~3) : 0;
    sh[tid] = v;
    __syncthreads();
#pragma unroll
    for (int d = 1; d < 1024; d <<= 1) {
        int t = (tid >= d) ? sh[tid - d] : 0;
        __syncthreads();
        sh[tid] += t;
        __syncthreads();
    }
    if (i < n) g_off[i] = sh[tid] - v;
    if (tid == 1023) g_bsum[blockIdx.x] = sh[1023];
}

// launch 3: per-block prefix over block sums, then offset slice
__global__ void k_scan23(int n, int nb) {
    __shared__ int spre;
    int tid = threadIdx.x;
    if (tid < 32) {
        int p = 0;
        for (int k = tid; k < blockIdx.x; k += 32) p += g_bsum[k];
#pragma unroll
        for (int o = 16; o; o >>= 1) p += __shfl_down_sync(0xffffffffu, p, o);
        if (tid == 0) spre = p;
    }
    __syncthreads();
    int i = blockIdx.x * 1024 + tid;
    if (i < n) g_off[i] += spre;
}

// launch 4 (ncu slot): CSR bucket fill
__global__ void k_fill(const void* __restrict__ ei, int E) {
    __shared__ int sh;
    int is64 = block_is64((const int*)ei, &sh);
    int e = blockIdx.x * blockDim.x + threadIdx.x;
    if (e >= E) return;
    int r, c;
    if (is64) {
        const long long* p = (const long long*)ei;
        r = (int)p[e]; c = (int)p[E + e];
    } else {
        const int* p = (const int*)ei;
        r = p[e]; c = p[E + e];
    }
    int pos = g_off[c] + atomicAdd(&g_cur[c], 1);
    g_csr[pos] = r;
}

// launch 5: dinv + xt = dinv * x (2 features)
__global__ void k_xt(const float* __restrict__ x, int n) {
    int node = blockIdx.x * blockDim.x + threadIdx.x;
    if (node >= n) return;
    float d = rsqrtf((float)(g_deg[node] + 1));
    g_dinv[node] = d;
    float2 xv = *(const float2*)&x[2 * node];
    g_xt[node] = make_float2(d * xv.x, d * xv.y);
}

// launch 6: warp/node. Lane-parallel 8B gather of xt (GCN1 in input space),
// then h1 = relu(dinv*(agg@W1)+b1), GAT linear, attention dots, global max.
__global__ void k_layer1(const float* __restrict__ W1, const float* __restrict__ b1,
                         const float* __restrict__ Wg,
                         const float* __restrict__ attS, const float* __restrict__ attD, int n) {
    __shared__ float sWg[32 * 64];
    __shared__ unsigned smax[2];
    int tid = threadIdx.x;
    for (int i = tid; i < 2048; i += blockDim.x) sWg[i] = Wg[i];
    if (tid < 2) smax[tid] = 0u;
    __syncthreads();

    int node = (blockIdx.x * blockDim.x + tid) >> 5;
    int lane = tid & 31;
    if (node < n) {
        int off = g_off[node], deg = g_deg[node];
        float ax = 0.f, ay = 0.f;
        for (int base = 0; base < deg; base += 32) {
            if (base + lane < deg) {
                int r = g_csr[off + base + lane];
                float2 v = g_xt[r];
                ax += v.x; ay += v.y;
            }
        }
#pragma unroll
        for (int o = 16; o; o >>= 1) {
            ax += __shfl_xor_sync(0xffffffffu, ax, o);
            ay += __shfl_xor_sync(0xffffffffu, ay, o);
        }
        float2 self = g_xt[node];
        float d = g_dinv[node];
        ax = d * (ax + self.x);
        ay = d * (ay + self.y);

        // h1[lane] = relu(ax*W1[0][lane] + ay*W1[1][lane] + b1[lane])
        float h1 = fmaxf(fmaf(ax, W1[lane], fmaf(ay, W1[32 + lane], b1[lane])), 0.f);

        float o0 = 0.f, o1 = 0.f;
#pragma unroll
        for (int i = 0; i < 32; i++) {
            float hv = __shfl_sync(0xffffffffu, h1, i);
            o0 = fmaf(hv, sWg[i * 64 + lane], o0);
            o1 = fmaf(hv, sWg[i * 64 + 32 + lane], o1);
        }
        g_hgh[node * 64 + lane]      = __float2half(o0);
        g_hgh[node * 64 + 32 + lane] = __float2half(o1);

        float as0 = o0 * attS[lane];
        float as1 = o1 * attS[32 + lane];
        float ad0 = o0 * attD[lane];
        float ad1 = o1 * attD[32 + lane];
#pragma unroll
        for (int o = 16; o; o >>= 1) {
            as0 += __shfl_down_sync(0xffffffffu, as0, o);
            as1 += __shfl_down_sync(0xffffffffu, as1, o);
            ad0 += __shfl_down_sync(0xffffffffu, ad0, o);
            ad1 += __shfl_down_sync(0xffffffffu, ad1, o);
        }
        if (lane == 0) {
            g_asrc[node * 2]     = as0;
            g_asrc[node * 2 + 1] = as1;
            g_adst[node * 2]     = ad0;
            g_adst[node * 2 + 1] = ad1;
            atomicMax(&smax[0], encf(as0));
            atomicMax(&smax[1], encf(as1));
        }
    }
    __syncthreads();
    if (tid < 2) atomicMax(&g_gmaxe[tid], smax[tid]);
}

// launch 7: warp/node GAT: lane-parallel softmax weights, shfl-broadcast aggregate
__global__ void k_gat(const float* __restrict__ gat_b, const float* __restrict__ W2, int n) {
    int tid = threadIdx.x;
    int node = (blockIdx.x * blockDim.x + tid) >> 5;
    int lane = tid & 31;
    if (node >= n) return;
    bool head1 = lane >= 16;
    int ch = (lane & 15) * 2;
    const unsigned* hgu = (const unsigned*)g_hgh;

    float2 ad = *(const float2*)&g_adst[2 * node];
    float2 as = *(const float2*)&g_asrc[2 * node];
    float m0 = lrelu(decf(g_gmaxe[0]) + ad.x);
    float m1 = lrelu(decf(g_gmaxe[1]) + ad.y);
    float m  = head1 ? m1 : m0;
    float es = head1 ? lrelu(as.y + ad.y) : lrelu(as.x + ad.x);
    float exs = __expf(es - m);

    unsigned hv = hgu[node * 32 + lane];
    float2 hf = __half22float2(*(const __half2*)&hv);
    float s = exs;
    float accx = exs * hf.x, accy = exs * hf.y;

    int off = g_off[node], deg = g_deg[node];
    for (int base = 0; base < deg; base += 32) {
        int cnt = min(32, deg - base);
        int r_l = g_csr[off + base + ((lane < cnt) ? lane : 0)];
        float2 asl = *(const float2*)&g_asrc[2 * r_l];
        float exA = __expf(lrelu(asl.x + ad.x) - m0);
        float exB = __expf(lrelu(asl.y + ad.y) - m1);
#pragma unroll 4
        for (int k = 0; k < cnt; k++) {
            int r = __shfl_sync(0xffffffffu, r_l, k);
            float w0 = __shfl_sync(0xffffffffu, exA, k);
            float w1 = __shfl_sync(0xffffffffu, exB, k);
            float w = head1 ? w1 : w0;
            unsigned h = hgu[r * 32 + lane];
            float2 f = __half22float2(*(const __half2*)&h);
            accx = fmaf(w, f.x, accx);
            accy = fmaf(w, f.y, accy);
            s += w;
        }
    }
    float vx = accx / s;
    float vy = accy / s;

    float ox = __shfl_down_sync(0xffffffffu, vx, 16);
    float oy = __shfl_down_sync(0xffffffffu, vy, 16);
    float c0 = fmaxf(fmaf(0.5f, vx + ox, gat_b[ch]),     0.f);
    float c1 = fmaxf(fmaf(0.5f, vy + oy, gat_b[ch + 1]), 0.f);
    float zi = fmaf(c0, W2[ch], c1 * W2[ch + 1]);
#pragma unroll
    for (int o = 8; o; o >>= 1)
        zi += __shfl_down_sync(0xffffffffu, zi, o);
    if (lane == 0) g_z[node] = g_dinv[node] * zi;
}

// launch 8: warp/node GCN2 gather + output; tail-resets counters for next call
__global__ void k_gcn2(float* __restrict__ out, const float* __restrict__ b2, int n) {
    int tid = threadIdx.x;
    int gid = blockIdx.x * blockDim.x + tid;
    int node = gid >> 5;
    int lane = tid & 31;
    if (node >= n) return;
    float s = (lane == 0) ? g_z[node] : 0.f;
    int off = g_off[node], end = off + g_deg[node];
    for (int j = off + lane; j < end; j += 32)
        s += g_z[g_csr[j]];
#pragma unroll
    for (int o = 16; o; o >>= 1)
        s += __shfl_down_sync(0xffffffffu, s, o);
    if (lane == 0) {
        out[node] = fmaf(g_dinv[node], s, b2[0]);
        g_deg[node] = 0;
        g_cur[node] = 0;
        if (node == 0) { g_gmaxe[0] = 0u; g_gmaxe[1] = 0u; }
    }
}

// ---------------- launch ----------------
extern "C" void kernel_launch(void* const* d_in, const int* in_sizes, int n_in,
                              void* d_out, int out_size) {
    const float* x    = (const float*)d_in[0];
    const void*  ei   = d_in[1];
    const float* W1   = (const float*)d_in[2];
    const float* b1   = (const float*)d_in[3];
    const float* Wg   = (const float*)d_in[4];
    const float* attS = (const float*)d_in[5];
    const float* attD = (const float*)d_in[6];
    const float* gb   = (const float*)d_in[7];
    const float* W2   = (const float*)d_in[8];
    const float* b2   = (const float*)d_in[9];
    float* out = (float*)d_out;

    int n = in_sizes[0] / 2;
    int E = in_sizes[1] / 2;
    const int T = 256;
    int nb = (n + 1023) / 1024;

    k_degcount<<<(E + T - 1) / T, T>>>(ei, E);
    k_scan1<<<nb, 1024>>>(n);
    k_scan23<<<nb, 1024>>>(n, nb);
    k_fill<<<(E + T - 1) / T, T>>>(ei, E);
    k_xt<<<(n + T - 1) / T, T>>>(x, n);
    k_layer1<<<(n * 32 + T - 1) / T, T>>>(W1, b1, Wg, attS, attD, n);
    k_gat<<<(n * 32 + T - 1) / T, T>>>(gb, W2, n);
    k_gcn2<<<(n * 32 + T - 1) / T, T>>>(out, b2, n);
}

// round 10
// speedup vs baseline: 1.2884x; 1.0012x over previous
#include <cuda_runtime.h>
#include <cuda_fp16.h>
#include <cuda_bf16.h>

// RoadGNN: GCN(2->32) -> ReLU -> GAT(32->2x32, mean heads) -> ReLU -> GCN(32->1)
// Counting-sort CSR build with ranks precomputed in the degree pass (atomic-free fill),
// GCN1 aggregated in input space, fp16 GAT gathers, 7 launches.

#define MAXN 100000
#define MAXE 1600000
#define MAXEP (MAXE + 3 * MAXN + 32)

// ---------------- scratch ----------------
__device__ int      g_deg[MAXN];        // zeroed by k_gcn2 tail each call
__device__ int      g_off[MAXN];
__device__ int      g_pos[MAXE];        // per-edge rank within its dst bucket
__device__ __align__(16) int g_csr[MAXEP];
__device__ int      g_bsum[128];
__device__ float    g_dinv[MAXN];
__device__ __align__(8) float2 g_xt[MAXN];   // dinv[n] * x[n]
__device__ __half   g_hgh[MAXN * 64];        // GAT linear out fp16 (h0|h1)
__device__ float    g_asrc[MAXN * 2];
__device__ float    g_adst[MAXN * 2];
__device__ unsigned g_gmaxe[2];         // zeroed by k_gcn2 tail each call
__device__ float    g_z[MAXN];

// ---------------- helpers ----------------
__device__ __forceinline__ float lrelu(float v) { return v > 0.f ? v : 0.2f * v; }
__device__ __forceinline__ unsigned encf(float f) {
    unsigned u = __float_as_uint(f);
    return (u & 0x80000000u) ? ~u : (u | 0x80000000u);
}
__device__ __forceinline__ float decf(unsigned u) {
    return __uint_as_float((u & 0x80000000u) ? (u & 0x7fffffffu) : ~u);
}
__device__ __forceinline__ int block_is64(const int* ei32, int* sh) {
    if (threadIdx.x == 0) {
        int is64 = 1;
        for (int i = 0; i < 64; i++)
            if (ei32[2 * i + 1] != 0) { is64 = 0; break; }
        *sh = is64;
    }
    __syncthreads();
    return *sh;
}

// ---------------- kernels ----------------

// launch 1: in-degree count + per-edge rank (streaming write)
__global__ void k_degcount(const void* __restrict__ ei, int E) {
    __shared__ int sh;
    int is64 = block_is64((const int*)ei, &sh);
    int e = blockIdx.x * blockDim.x + threadIdx.x;
    if (e >= E) return;
    int c;
    if (is64) c = (int)((const long long*)ei)[E + e];
    else      c = ((const int*)ei)[E + e];
    g_pos[e] = atomicAdd(&g_deg[c], 1);
}

// launch 2: block-local scan of 4-padded degrees
__global__ void k_scan1(int n) {
    __shared__ int sh[1024];
    int tid = threadIdx.x;
    int i = blockIdx.x * 1024 + tid;
    int v = (i < n) ? ((g_deg[i] + 3) & ~3) : 0;
    sh[tid] = v;
    __syncthreads();
#pragma unroll
    for (int d = 1; d < 1024; d <<= 1) {
        int t = (tid >= d) ? sh[tid - d] : 0;
        __syncthreads();
        sh[tid] += t;
        __syncthreads();
    }
    if (i < n) g_off[i] = sh[tid] - v;
    if (tid == 1023) g_bsum[blockIdx.x] = sh[1023];
}

// launch 3: finish scan; also compute dinv + xt (deg is final)
__global__ void k_scan23(const float* __restrict__ x, int n, int nb) {
    __shared__ int spre;
    int tid = threadIdx.x;
    if (tid < 32) {
        int p = 0;
        for (int k = tid; k < blockIdx.x; k += 32) p += g_bsum[k];
#pragma unroll
        for (int o = 16; o; o >>= 1) p += __shfl_down_sync(0xffffffffu, p, o);
        if (tid == 0) spre = p;
    }
    __syncthreads();
    int i = blockIdx.x * 1024 + tid;
    if (i < n) {
        g_off[i] += spre;
        float d = rsqrtf((float)(g_deg[i] + 1));
        g_dinv[i] = d;
        float2 xv = *(const float2*)&x[2 * i];
        g_xt[i] = make_float2(d * xv.x, d * xv.y);
    }
}

// launch 4 (ncu slot): CSR fill — NO atomics, rank precomputed
__global__ void k_fill(const void* __restrict__ ei, int E) {
    __shared__ int sh;
    int is64 = block_is64((const int*)ei, &sh);
    int e = blockIdx.x * blockDim.x + threadIdx.x;
    if (e >= E) return;
    int r, c;
    if (is64) {
        const long long* p = (const long long*)ei;
        r = (int)p[e]; c = (int)p[E + e];
    } else {
        const int* p = (const int*)ei;
        r = p[e]; c = p[E + e];
    }
    g_csr[g_off[c] + g_pos[e]] = r;
}

// launch 5: warp/node. Lane-parallel xt gather (GCN1 in input space),
// h1 = relu(dinv*(agg@W1)+b1), GAT linear, attention dots, global max.
__global__ void k_layer1(const float* __restrict__ W1, const float* __restrict__ b1,
                         const float* __restrict__ Wg,
                         const float* __restrict__ attS, const float* __restrict__ attD, int n) {
    __shared__ float sWg[32 * 64];
    __shared__ unsigned smax[2];
    int tid = threadIdx.x;
    for (int i = tid; i < 2048; i += blockDim.x) sWg[i] = Wg[i];
    if (tid < 2) smax[tid] = 0u;
    __syncthreads();

    int node = (blockIdx.x * blockDim.x + tid) >> 5;
    int lane = tid & 31;
    if (node < n) {
        int off = g_off[node], deg = g_deg[node];
        float ax = 0.f, ay = 0.f;
        for (int base = 0; base < deg; base += 32) {
            if (base + lane < deg) {
                int r = g_csr[off + base + lane];
                float2 v = g_xt[r];
                ax += v.x; ay += v.y;
            }
        }
#pragma unroll
        for (int o = 16; o; o >>= 1) {
            ax += __shfl_xor_sync(0xffffffffu, ax, o);
            ay += __shfl_xor_sync(0xffffffffu, ay, o);
        }
        float2 self = g_xt[node];
        float d = g_dinv[node];
        ax = d * (ax + self.x);
        ay = d * (ay + self.y);

        float h1 = fmaxf(fmaf(ax, W1[lane], fmaf(ay, W1[32 + lane], b1[lane])), 0.f);

        float o0 = 0.f, o1 = 0.f;
#pragma unroll
        for (int i = 0; i < 32; i++) {
            float hv = __shfl_sync(0xffffffffu, h1, i);
            o0 = fmaf(hv, sWg[i * 64 + lane], o0);
            o1 = fmaf(hv, sWg[i * 64 + 32 + lane], o1);
        }
        g_hgh[node * 64 + lane]      = __float2half(o0);
        g_hgh[node * 64 + 32 + lane] = __float2half(o1);

        float as0 = o0 * attS[lane];
        float as1 = o1 * attS[32 + lane];
        float ad0 = o0 * attD[lane];
        float ad1 = o1 * attD[32 + lane];
#pragma unroll
        for (int o = 16; o; o >>= 1) {
            as0 += __shfl_down_sync(0xffffffffu, as0, o);
            as1 += __shfl_down_sync(0xffffffffu, as1, o);
            ad0 += __shfl_down_sync(0xffffffffu, ad0, o);
            ad1 += __shfl_down_sync(0xffffffffu, ad1, o);
        }
        if (lane == 0) {
            g_asrc[node * 2]     = as0;
            g_asrc[node * 2 + 1] = as1;
            g_adst[node * 2]     = ad0;
            g_adst[node * 2 + 1] = ad1;
            atomicMax(&smax[0], encf(as0));
            atomicMax(&smax[1], encf(as1));
        }
    }
    __syncthreads();
    if (tid < 2) atomicMax(&g_gmaxe[tid], smax[tid]);
}

// launch 6: warp/node GAT. Lane-parallel softmax weights; paired broadcast loop.
// Head weights are shuffled SEPARATELY and selected per-lane AFTER the shuffle
// (selecting before the shuffle mixes heads — R9 bug).
__global__ void k_gat(const float* __restrict__ gat_b, const float* __restrict__ W2, int n) {
    int tid = threadIdx.x;
    int node = (blockIdx.x * blockDim.x + tid) >> 5;
    int lane = tid & 31;
    if (node >= n) return;
    bool head1 = lane >= 16;
    int ch = (lane & 15) * 2;
    const unsigned* hgu = (const unsigned*)g_hgh;

    float2 ad = *(const float2*)&g_adst[2 * node];
    float2 as = *(const float2*)&g_asrc[2 * node];
    float m0 = lrelu(decf(g_gmaxe[0]) + ad.x);
    float m1 = lrelu(decf(g_gmaxe[1]) + ad.y);
    float m  = head1 ? m1 : m0;
    float es = head1 ? lrelu(as.y + ad.y) : lrelu(as.x + ad.x);
    float exs = __expf(es - m);

    unsigned hv = hgu[node * 32 + lane];
    float2 hf = __half22float2(*(const __half2*)&hv);
    float s = exs, s2 = 0.f;
    float accx = exs * hf.x, accy = exs * hf.y;
    float acc2x = 0.f, acc2y = 0.f;

    int off = g_off[node], deg = g_deg[node];
    for (int base = 0; base < deg; base += 32) {
        int cnt = min(32, deg - base);
        int r_l = g_csr[off + base + ((lane < cnt) ? lane : 0)];
        float2 asl = *(const float2*)&g_asrc[2 * r_l];
        float exA = __expf(lrelu(asl.x + ad.x) - m0);
        float exB = __expf(lrelu(asl.y + ad.y) - m1);
        int k = 0;
        for (; k + 1 < cnt; k += 2) {
            int r0 = __shfl_sync(0xffffffffu, r_l, k);
            int r1 = __shfl_sync(0xffffffffu, r_l, k + 1);
            float wA0 = __shfl_sync(0xffffffffu, exA, k);
            float wB0 = __shfl_sync(0xffffffffu, exB, k);
            float wA1 = __shfl_sync(0xffffffffu, exA, k + 1);
            float wB1 = __shfl_sync(0xffffffffu, exB, k + 1);
            float w0 = head1 ? wB0 : wA0;
            float w1 = head1 ? wB1 : wA1;
            unsigned h0 = hgu[r0 * 32 + lane];
            unsigned h1 = hgu[r1 * 32 + lane];
            float2 f0 = __half22float2(*(const __half2*)&h0);
            float2 f1 = __half22float2(*(const __half2*)&h1);
            accx  = fmaf(w0, f0.x, accx);
            accy  = fmaf(w0, f0.y, accy);
            acc2x = fmaf(w1, f1.x, acc2x);
            acc2y = fmaf(w1, f1.y, acc2y);
            s += w0; s2 += w1;
        }
        if (k < cnt) {
            int r0 = __shfl_sync(0xffffffffu, r_l, k);
            float wA0 = __shfl_sync(0xffffffffu, exA, k);
            float wB0 = __shfl_sync(0xffffffffu, exB, k);
            float w0 = head1 ? wB0 : wA0;
            unsigned h0 = hgu[r0 * 32 + lane];
            float2 f0 = __half22float2(*(const __half2*)&h0);
            accx = fmaf(w0, f0.x, accx);
            accy = fmaf(w0, f0.y, accy);
            s += w0;
        }
    }
    float st = s + s2;
    float vx = (accx + acc2x) / st;
    float vy = (accy + acc2y) / st;

    float ox = __shfl_down_sync(0xffffffffu, vx, 16);
    float oy = __shfl_down_sync(0xffffffffu, vy, 16);
    float c0 = fmaxf(fmaf(0.5f, vx + ox, gat_b[ch]),     0.f);
    float c1 = fmaxf(fmaf(0.5f, vy + oy, gat_b[ch + 1]), 0.f);
    float zi = fmaf(c0, W2[ch], c1 * W2[ch + 1]);
#pragma unroll
    for (int o = 8; o; o >>= 1)
        zi += __shfl_down_sync(0xffffffffu, zi, o);
    if (lane == 0) g_z[node] = g_dinv[node] * zi;
}

// launch 7: warp/node GCN2 gather + output; tail-resets counters
__global__ void k_gcn2(float* __restrict__ out, const float* __restrict__ b2, int n) {
    int tid = threadIdx.x;
    int gid = blockIdx.x * blockDim.x + tid;
    int node = gid >> 5;
    int lane = tid & 31;
    if (node >= n) return;
    float s = (lane == 0) ? g_z[node] : 0.f;
    int off = g_off[node], end = off + g_deg[node];
    for (int j = off + lane; j < end; j += 32)
        s += g_z[g_csr[j]];
#pragma unroll
    for (int o = 16; o; o >>= 1)
        s += __shfl_down_sync(0xffffffffu, s, o);
    if (lane == 0) {
        out[node] = fmaf(g_dinv[node], s, b2[0]);
        g_deg[node] = 0;
        if (node == 0) { g_gmaxe[0] = 0u; g_gmaxe[1] = 0u; }
    }
}

// ---------------- launch ----------------
extern "C" void kernel_launch(void* const* d_in, const int* in_sizes, int n_in,
                              void* d_out, int out_size) {
    const float* x    = (const float*)d_in[0];
    const void*  ei   = d_in[1];
    const float* W1   = (const float*)d_in[2];
    const float* b1   = (const float*)d_in[3];
    const float* Wg   = (const float*)d_in[4];
    const float* attS = (const float*)d_in[5];
    const float* attD = (const float*)d_in[6];
    const float* gb   = (const float*)d_in[7];
    const float* W2   = (const float*)d_in[8];
    const float* b2   = (const float*)d_in[9];
    float* out = (float*)d_out;

    int n = in_sizes[0] / 2;
    int E = in_sizes[1] / 2;
    const int T = 256;
    int nb = (n + 1023) / 1024;

    k_degcount<<<(E + T - 1) / T, T>>>(ei, E);
    k_scan1<<<nb, 1024>>>(n);
    k_scan23<<<nb, 1024>>>(x, n, nb);
    k_fill<<<(E + T - 1) / T, T>>>(ei, E);
    k_layer1<<<(n * 32 + T - 1) / T, T>>>(W1, b1, Wg, attS, attD, n);
    k_gat<<<(n * 32 + T - 1) / T, T>>>(gb, W2, n);
    k_gcn2<<<(n * 32 + T - 1) / T, T>>>(out, b2, n);
}

// round 11
// speedup vs baseline: 1.3023x; 1.0108x over previous
#include <cuda_runtime.h>
#include <cuda_fp16.h>
#include <cuda_bf16.h>

// RoadGNN: GCN(2->32) -> ReLU -> GAT(32->2x32, mean heads) -> ReLU -> GCN(32->1)
// Counting-sort CSR (rank precomputed, atomic-free fill), GCN1 in input space,
// fp16 GAT gathers with unroll-4 broadcast loop and hoisted softmax sums.

#define MAXN 100000
#define MAXE 1600000
#define MAXEP (MAXE + 3 * MAXN + 32)

// ---------------- scratch ----------------
__device__ int      g_deg[MAXN];        // zeroed by k_gcn2 tail each call
__device__ int      g_off[MAXN];
__device__ int      g_pos[MAXE];        // per-edge rank within its dst bucket
__device__ __align__(16) int g_csr[MAXEP];
__device__ int      g_bsum[128];
__device__ float    g_dinv[MAXN];
__device__ __align__(8) float2 g_xt[MAXN];   // dinv[n] * x[n]
__device__ __half   g_hgh[MAXN * 64];        // GAT linear out fp16 (h0|h1)
__device__ float    g_asrc[MAXN * 2];
__device__ float    g_adst[MAXN * 2];
__device__ unsigned g_gmaxe[2];         // zeroed by k_gcn2 tail each call
__device__ float    g_z[MAXN];

// ---------------- helpers ----------------
__device__ __forceinline__ float lrelu(float v) { return v > 0.f ? v : 0.2f * v; }
__device__ __forceinline__ unsigned encf(float f) {
    unsigned u = __float_as_uint(f);
    return (u & 0x80000000u) ? ~u : (u | 0x80000000u);
}
__device__ __forceinline__ float decf(unsigned u) {
    return __uint_as_float((u & 0x80000000u) ? (u & 0x7fffffffu) : ~u);
}
// warp-ballot dtype detect: int64 nonneg < 2^31 => odd int32 words all zero
__device__ __forceinline__ int block_is64(const int* ei32, int* sh) {
    if (threadIdx.x < 32) {
        int bad = (ei32[2 * threadIdx.x + 1] != 0);
        unsigned b = __ballot_sync(0xffffffffu, bad);
        if (threadIdx.x == 0) *sh = (b == 0u);
    }
    __syncthreads();
    return *sh;
}

// ---------------- kernels ----------------

// launch 1: in-degree count + per-edge rank (streaming write)
__global__ void k_degcount(const void* __restrict__ ei, int E) {
    __shared__ int sh;
    int is64 = block_is64((const int*)ei, &sh);
    int e = blockIdx.x * blockDim.x + threadIdx.x;
    if (e >= E) return;
    int c;
    if (is64) c = (int)((const long long*)ei)[E + e];
    else      c = ((const int*)ei)[E + e];
    g_pos[e] = atomicAdd(&g_deg[c], 1);
}

// launch 2: block-local scan of 4-padded degrees
__global__ void k_scan1(int n) {
    __shared__ int sh[1024];
    int tid = threadIdx.x;
    int i = blockIdx.x * 1024 + tid;
    int v = (i < n) ? ((g_deg[i] + 3) & ~3) : 0;
    sh[tid] = v;
    __syncthreads();
#pragma unroll
    for (int d = 1; d < 1024; d <<= 1) {
        int t = (tid >= d) ? sh[tid - d] : 0;
        __syncthreads();
        sh[tid] += t;
        __syncthreads();
    }
    if (i < n) g_off[i] = sh[tid] - v;
    if (tid == 1023) g_bsum[blockIdx.x] = sh[1023];
}

// launch 3: finish scan; also compute dinv + xt (deg final here)
__global__ void k_scan23(const float* __restrict__ x, int n, int nb) {
    __shared__ int spre;
    int tid = threadIdx.x;
    if (tid < 32) {
        int p = 0;
        for (int k = tid; k < blockIdx.x; k += 32) p += g_bsum[k];
#pragma unroll
        for (int o = 16; o; o >>= 1) p += __shfl_down_sync(0xffffffffu, p, o);
        if (tid == 0) spre = p;
    }
    __syncthreads();
    int i = blockIdx.x * 1024 + tid;
    if (i < n) {
        g_off[i] += spre;
        float d = rsqrtf((float)(g_deg[i] + 1));
        g_dinv[i] = d;
        float2 xv = *(const float2*)&x[2 * i];
        g_xt[i] = make_float2(d * xv.x, d * xv.y);
    }
}

// launch 4 (ncu slot): CSR fill — NO atomics, rank precomputed
__global__ void k_fill(const void* __restrict__ ei, int E) {
    __shared__ int sh;
    int is64 = block_is64((const int*)ei, &sh);
    int e = blockIdx.x * blockDim.x + threadIdx.x;
    if (e >= E) return;
    int r, c;
    if (is64) {
        const long long* p = (const long long*)ei;
        r = (int)p[e]; c = (int)p[E + e];
    } else {
        const int* p = (const int*)ei;
        r = p[e]; c = p[E + e];
    }
    g_csr[g_off[c] + g_pos[e]] = r;
}

// launch 5: warp/node. Lane-parallel xt gather (GCN1 in input space),
// h1 = relu(dinv*(agg@W1)+b1), GAT linear, attention dots, global max.
__global__ void k_layer1(const float* __restrict__ W1, const float* __restrict__ b1,
                         const float* __restrict__ Wg,
                         const float* __restrict__ attS, const float* __restrict__ attD, int n) {
    __shared__ float sWg[32 * 64];
    __shared__ unsigned smax[2];
    int tid = threadIdx.x;
    for (int i = tid; i < 2048; i += blockDim.x) sWg[i] = Wg[i];
    if (tid < 2) smax[tid] = 0u;
    __syncthreads();

    int node = (blockIdx.x * blockDim.x + tid) >> 5;
    int lane = tid & 31;
    if (node < n) {
        int off = g_off[node], deg = g_deg[node];
        float ax = 0.f, ay = 0.f;
        for (int base = 0; base < deg; base += 32) {
            if (base + lane < deg) {
                int r = g_csr[off + base + lane];
                float2 v = g_xt[r];
                ax += v.x; ay += v.y;
            }
        }
#pragma unroll
        for (int o = 16; o; o >>= 1) {
            ax += __shfl_xor_sync(0xffffffffu, ax, o);
            ay += __shfl_xor_sync(0xffffffffu, ay, o);
        }
        float2 self = g_xt[node];
        float d = g_dinv[node];
        ax = d * (ax + self.x);
        ay = d * (ay + self.y);

        float h1 = fmaxf(fmaf(ax, W1[lane], fmaf(ay, W1[32 + lane], b1[lane])), 0.f);

        float o0 = 0.f, o1 = 0.f;
#pragma unroll
        for (int i = 0; i < 32; i++) {
            float hv = __shfl_sync(0xffffffffu, h1, i);
            o0 = fmaf(hv, sWg[i * 64 + lane], o0);
            o1 = fmaf(hv, sWg[i * 64 + 32 + lane], o1);
        }
        g_hgh[node * 64 + lane]      = __float2half(o0);
        g_hgh[node * 64 + 32 + lane] = __float2half(o1);

        float as0 = o0 * attS[lane];
        float as1 = o1 * attS[32 + lane];
        float ad0 = o0 * attD[lane];
        float ad1 = o1 * attD[32 + lane];
#pragma unroll
        for (int o = 16; o; o >>= 1) {
            as0 += __shfl_down_sync(0xffffffffu, as0, o);
            as1 += __shfl_down_sync(0xffffffffu, as1, o);
            ad0 += __shfl_down_sync(0xffffffffu, ad0, o);
            ad1 += __shfl_down_sync(0xffffffffu, ad1, o);
        }
        if (lane == 0) {
            g_asrc[node * 2]     = as0;
            g_asrc[node * 2 + 1] = as1;
            g_adst[node * 2]     = ad0;
            g_adst[node * 2 + 1] = ad1;
            atomicMax(&smax[0], encf(as0));
            atomicMax(&smax[1], encf(as1));
        }
    }
    __syncthreads();
    if (tid < 2) atomicMax(&g_gmaxe[tid], smax[tid]);
}

// launch 6: warp/node GAT. Phase A: lane-parallel exp weights + lane-local s sums.
// Phase B: unroll-4 broadcast loop, 4 independent 128B fp16 gathers in flight.
// Head weights shuffled separately, selected after the shuffle.
__global__ void k_gat(const float* __restrict__ gat_b, const float* __restrict__ W2, int n) {
    int tid = threadIdx.x;
    int node = (blockIdx.x * blockDim.x + tid) >> 5;
    int lane = tid & 31;
    if (node >= n) return;
    bool head1 = lane >= 16;
    int ch = (lane & 15) * 2;
    const unsigned* hgu = (const unsigned*)g_hgh;

    float2 ad = *(const float2*)&g_adst[2 * node];
    float2 as = *(const float2*)&g_asrc[2 * node];
    float m0 = lrelu(decf(g_gmaxe[0]) + ad.x);
    float m1 = lrelu(decf(g_gmaxe[1]) + ad.y);
    float m  = head1 ? m1 : m0;
    float es = head1 ? lrelu(as.y + ad.y) : lrelu(as.x + ad.x);
    float exs = __expf(es - m);

    unsigned hv = hgu[node * 32 + lane];
    float2 hf = __half22float2(*(const __half2*)&hv);
    float accx = exs * hf.x, accy = exs * hf.y;   // self-loop term
    float acc2x = 0.f, acc2y = 0.f;
    float sA_acc = 0.f, sB_acc = 0.f;             // lane-local edge exp sums

    int off = g_off[node], deg = g_deg[node];
    for (int base = 0; base < deg; base += 32) {
        int cnt = min(32, deg - base);
        bool valid = lane < cnt;
        int r_l = g_csr[off + base + (valid ? lane : 0)];
        float2 asl = *(const float2*)&g_asrc[2 * r_l];
        float exA = valid ? __expf(lrelu(asl.x + ad.x) - m0) : 0.f;
        float exB = valid ? __expf(lrelu(asl.y + ad.y) - m1) : 0.f;
        sA_acc += exA;
        sB_acc += exB;
        int k = 0;
        for (; k + 3 < cnt; k += 4) {
            int r0 = __shfl_sync(0xffffffffu, r_l, k);
            int r1 = __shfl_sync(0xffffffffu, r_l, k + 1);
            int r2 = __shfl_sync(0xffffffffu, r_l, k + 2);
            int r3 = __shfl_sync(0xffffffffu, r_l, k + 3);
            unsigned h0 = hgu[r0 * 32 + lane];
            unsigned h1 = hgu[r1 * 32 + lane];
            unsigned h2 = hgu[r2 * 32 + lane];
            unsigned h3 = hgu[r3 * 32 + lane];
            float wA0 = __shfl_sync(0xffffffffu, exA, k);
            float wB0 = __shfl_sync(0xffffffffu, exB, k);
            float wA1 = __shfl_sync(0xffffffffu, exA, k + 1);
            float wB1 = __shfl_sync(0xffffffffu, exB, k + 1);
            float wA2 = __shfl_sync(0xffffffffu, exA, k + 2);
            float wB2 = __shfl_sync(0xffffffffu, exB, k + 2);
            float wA3 = __shfl_sync(0xffffffffu, exA, k + 3);
            float wB3 = __shfl_sync(0xffffffffu, exB, k + 3);
            float w0 = head1 ? wB0 : wA0;
            float w1 = head1 ? wB1 : wA1;
            float w2 = head1 ? wB2 : wA2;
            float w3 = head1 ? wB3 : wA3;
            float2 f0 = __half22float2(*(const __half2*)&h0);
            float2 f1 = __half22float2(*(const __half2*)&h1);
            float2 f2 = __half22float2(*(const __half2*)&h2);
            float2 f3 = __half22float2(*(const __half2*)&h3);
            accx  = fmaf(w0, f0.x, accx);
            accy  = fmaf(w0, f0.y, accy);
            acc2x = fmaf(w1, f1.x, acc2x);
            acc2y = fmaf(w1, f1.y, acc2y);
            accx  = fmaf(w2, f2.x, accx);
            accy  = fmaf(w2, f2.y, accy);
            acc2x = fmaf(w3, f3.x, acc2x);
            acc2y = fmaf(w3, f3.y, acc2y);
        }
        for (; k < cnt; k++) {
            int r0 = __shfl_sync(0xffffffffu, r_l, k);
            float wA0 = __shfl_sync(0xffffffffu, exA, k);
            float wB0 = __shfl_sync(0xffffffffu, exB, k);
            float w0 = head1 ? wB0 : wA0;
            unsigned h0 = hgu[r0 * 32 + lane];
            float2 f0 = __half22float2(*(const __half2*)&h0);
            accx = fmaf(w0, f0.x, accx);
            accy = fmaf(w0, f0.y, accy);
        }
    }
    // warp-reduce the per-head softmax sums (every lane contributed one edge per chunk)
#pragma unroll
    for (int o = 16; o; o >>= 1) {
        sA_acc += __shfl_xor_sync(0xffffffffu, sA_acc, o);
        sB_acc += __shfl_xor_sync(0xffffffffu, sB_acc, o);
    }
    float st = (head1 ? sB_acc : sA_acc) + exs;
    float vx = (accx + acc2x) / st;
    float vy = (accy + acc2y) / st;

    float ox = __shfl_down_sync(0xffffffffu, vx, 16);
    float oy = __shfl_down_sync(0xffffffffu, vy, 16);
    float c0 = fmaxf(fmaf(0.5f, vx + ox, gat_b[ch]),     0.f);
    float c1 = fmaxf(fmaf(0.5f, vy + oy, gat_b[ch + 1]), 0.f);
    float zi = fmaf(c0, W2[ch], c1 * W2[ch + 1]);
#pragma unroll
    for (int o = 8; o; o >>= 1)
        zi += __shfl_down_sync(0xffffffffu, zi, o);
    if (lane == 0) g_z[node] = g_dinv[node] * zi;
}

// launch 7: warp/node GCN2 gather + output; tail-resets counters
__global__ void k_gcn2(float* __restrict__ out, const float* __restrict__ b2, int n) {
    int tid = threadIdx.x;
    int gid = blockIdx.x * blockDim.x + tid;
    int node = gid >> 5;
    int lane = tid & 31;
    if (node >= n) return;
    float s = (lane == 0) ? g_z[node] : 0.f;
    int off = g_off[node], end = off + g_deg[node];
    for (int j = off + lane; j < end; j += 32)
        s += g_z[g_csr[j]];
#pragma unroll
    for (int o = 16; o; o >>= 1)
        s += __shfl_down_sync(0xffffffffu, s, o);
    if (lane == 0) {
        out[node] = fmaf(g_dinv[node], s, b2[0]);
        g_deg[node] = 0;
        if (node == 0) { g_gmaxe[0] = 0u; g_gmaxe[1] = 0u; }
    }
}

// ---------------- launch ----------------
extern "C" void kernel_launch(void* const* d_in, const int* in_sizes, int n_in,
                              void* d_out, int out_size) {
    const float* x    = (const float*)d_in[0];
    const void*  ei   = d_in[1];
    const float* W1   = (const float*)d_in[2];
    const float* b1   = (const float*)d_in[3];
    const float* Wg   = (const float*)d_in[4];
    const float* attS = (const float*)d_in[5];
    const float* attD = (const float*)d_in[6];
    const float* gb   = (const float*)d_in[7];
    const float* W2   = (const float*)d_in[8];
    const float* b2   = (const float*)d_in[9];
    float* out = (float*)d_out;

    int n = in_sizes[0] / 2;
    int E = in_sizes[1] / 2;
    const int T = 256;
    int nb = (n + 1023) / 1024;

    k_degcount<<<(E + T - 1) / T, T>>>(ei, E);
    k_scan1<<<nb, 1024>>>(n);
    k_scan23<<<nb, 1024>>>(x, n, nb);
    k_fill<<<(E + T - 1) / T, T>>>(ei, E);
    k_layer1<<<(n * 32 + T - 1) / T, T>>>(W1, b1, Wg, attS, attD, n);
    k_gat<<<(n * 32 + T - 1) / T, T>>>(gb, W2, n);
    k_gcn2<<<(n * 32 + T - 1) / T, T>>>(out, b2, n);
}

// round 12
// speedup vs baseline: 1.3901x; 1.0674x over previous
#include <cuda_runtime.h>
#include <cuda_fp16.h>
#include <cuda_bf16.h>

// RoadGNN: GCN(2->32) -> ReLU -> GAT(32->2x32, mean heads) -> ReLU -> GCN(32->1)
// Counting-sort CSR (rank precomputed, atomic-free fill), GCN1 in input space,
// fp16 GAT gathers. GAT softmax weights via factored exponentials:
//   w(e) = exp(lrelu(as_r + ad_c))  [shift cancels in softmax]
//        = t>1 ? t^5 : t,  t = p[r]*q[c],  p = exp(0.2 as), q = exp(0.2 ad)
// -> zero MUFU in the edge loop.

#define MAXN 100000
#define MAXE 1600000
#define MAXEP (MAXE + 3 * MAXN + 32)

// ---------------- scratch ----------------
__device__ int      g_deg[MAXN];        // zeroed by k_gcn2 tail each call
__device__ int      g_off[MAXN];
__device__ int      g_pos[MAXE];        // per-edge rank within its dst bucket
__device__ __align__(16) int g_csr[MAXEP];
__device__ int      g_bsum[128];
__device__ float    g_dinv[MAXN];
__device__ __align__(8) float2 g_xt[MAXN];   // dinv[n] * x[n]
__device__ __half   g_hgh[MAXN * 64];        // GAT linear out fp16 (h0|h1)
__device__ __align__(8) float2 g_ps[MAXN];   // exp(0.2*a_src) per head
__device__ __align__(8) float2 g_qs[MAXN];   // exp(0.2*a_dst) per head
__device__ float    g_z[MAXN];

// ---------------- helpers ----------------
__device__ __forceinline__ float pow5(float t) { float t2 = t * t; return t2 * t2 * t; }
// warp-ballot dtype detect: int64 nonneg < 2^31 => odd int32 words all zero
__device__ __forceinline__ int block_is64(const int* ei32, int* sh) {
    if (threadIdx.x < 32) {
        int bad = (ei32[2 * threadIdx.x + 1] != 0);
        unsigned b = __ballot_sync(0xffffffffu, bad);
        if (threadIdx.x == 0) *sh = (b == 0u);
    }
    __syncthreads();
    return *sh;
}

// ---------------- kernels ----------------

// launch 1: in-degree count + per-edge rank (streaming write)
__global__ void k_degcount(const void* __restrict__ ei, int E) {
    __shared__ int sh;
    int is64 = block_is64((const int*)ei, &sh);
    int e = blockIdx.x * blockDim.x + threadIdx.x;
    if (e >= E) return;
    int c;
    if (is64) c = (int)((const long long*)ei)[E + e];
    else      c = ((const int*)ei)[E + e];
    g_pos[e] = atomicAdd(&g_deg[c], 1);
}

// launch 2: block-local scan of 4-padded degrees
__global__ void k_scan1(int n) {
    __shared__ int sh[1024];
    int tid = threadIdx.x;
    int i = blockIdx.x * 1024 + tid;
    int v = (i < n) ? ((g_deg[i] + 3) & ~3) : 0;
    sh[tid] = v;
    __syncthreads();
#pragma unroll
    for (int d = 1; d < 1024; d <<= 1) {
        int t = (tid >= d) ? sh[tid - d] : 0;
        __syncthreads();
        sh[tid] += t;
        __syncthreads();
    }
    if (i < n) g_off[i] = sh[tid] - v;
    if (tid == 1023) g_bsum[blockIdx.x] = sh[1023];
}

// launch 3: finish scan; also compute dinv + xt (deg final here)
__global__ void k_scan23(const float* __restrict__ x, int n, int nb) {
    __shared__ int spre;
    int tid = threadIdx.x;
    if (tid < 32) {
        int p = 0;
        for (int k = tid; k < blockIdx.x; k += 32) p += g_bsum[k];
#pragma unroll
        for (int o = 16; o; o >>= 1) p += __shfl_down_sync(0xffffffffu, p, o);
        if (tid == 0) spre = p;
    }
    __syncthreads();
    int i = blockIdx.x * 1024 + tid;
    if (i < n) {
        g_off[i] += spre;
        float d = rsqrtf((float)(g_deg[i] + 1));
        g_dinv[i] = d;
        float2 xv = *(const float2*)&x[2 * i];
        g_xt[i] = make_float2(d * xv.x, d * xv.y);
    }
}

// launch 4 (ncu slot): CSR fill — NO atomics, rank precomputed
__global__ void k_fill(const void* __restrict__ ei, int E) {
    __shared__ int sh;
    int is64 = block_is64((const int*)ei, &sh);
    int e = blockIdx.x * blockDim.x + threadIdx.x;
    if (e >= E) return;
    int r, c;
    if (is64) {
        const long long* p = (const long long*)ei;
        r = (int)p[e]; c = (int)p[E + e];
    } else {
        const int* p = (const int*)ei;
        r = p[e]; c = p[E + e];
    }
    g_csr[g_off[c] + g_pos[e]] = r;
}

// launch 5: warp/node. Lane-parallel xt gather (GCN1 in input space),
// h1 = relu(dinv*(agg@W1)+b1), GAT linear, p/q exp factors.
__global__ void k_layer1(const float* __restrict__ W1, const float* __restrict__ b1,
                         const float* __restrict__ Wg,
                         const float* __restrict__ attS, const float* __restrict__ attD, int n) {
    __shared__ float sWg[32 * 64];
    int tid = threadIdx.x;
    for (int i = tid; i < 2048; i += blockDim.x) sWg[i] = Wg[i];
    __syncthreads();

    int node = (blockIdx.x * blockDim.x + tid) >> 5;
    int lane = tid & 31;
    if (node >= n) return;

    int off = g_off[node], deg = g_deg[node];
    float ax = 0.f, ay = 0.f;
    for (int base = 0; base < deg; base += 32) {
        if (base + lane < deg) {
            int r = g_csr[off + base + lane];
            float2 v = g_xt[r];
            ax += v.x; ay += v.y;
        }
    }
#pragma unroll
    for (int o = 16; o; o >>= 1) {
        ax += __shfl_xor_sync(0xffffffffu, ax, o);
        ay += __shfl_xor_sync(0xffffffffu, ay, o);
    }
    float2 self = g_xt[node];
    float d = g_dinv[node];
    ax = d * (ax + self.x);
    ay = d * (ay + self.y);

    float h1 = fmaxf(fmaf(ax, W1[lane], fmaf(ay, W1[32 + lane], b1[lane])), 0.f);

    float o0 = 0.f, o1 = 0.f;
#pragma unroll
    for (int i = 0; i < 32; i++) {
        float hv = __shfl_sync(0xffffffffu, h1, i);
        o0 = fmaf(hv, sWg[i * 64 + lane], o0);
        o1 = fmaf(hv, sWg[i * 64 + 32 + lane], o1);
    }
    g_hgh[node * 64 + lane]      = __float2half(o0);
    g_hgh[node * 64 + 32 + lane] = __float2half(o1);

    float as0 = o0 * attS[lane];
    float as1 = o1 * attS[32 + lane];
    float ad0 = o0 * attD[lane];
    float ad1 = o1 * attD[32 + lane];
#pragma unroll
    for (int o = 16; o; o >>= 1) {
        as0 += __shfl_down_sync(0xffffffffu, as0, o);
        as1 += __shfl_down_sync(0xffffffffu, as1, o);
        ad0 += __shfl_down_sync(0xffffffffu, ad0, o);
        ad1 += __shfl_down_sync(0xffffffffu, ad1, o);
    }
    if (lane == 0) {
        g_ps[node] = make_float2(__expf(0.2f * as0), __expf(0.2f * as1));
        g_qs[node] = make_float2(__expf(0.2f * ad0), __expf(0.2f * ad1));
    }
}

// launch 6: warp/node GAT. Phase A: lane-parallel multiplicative weights
// (t = p[r]*q[c]; w = t>1 ? t^5 : t) + lane-local sums. Phase B: unroll-4
// broadcast loop with 4 independent 128B fp16 gathers in flight.
__global__ void k_gat(const float* __restrict__ gat_b, const float* __restrict__ W2, int n) {
    int tid = threadIdx.x;
    int node = (blockIdx.x * blockDim.x + tid) >> 5;
    int lane = tid & 31;
    if (node >= n) return;
    bool head1 = lane >= 16;
    int ch = (lane & 15) * 2;
    const unsigned* hgu = (const unsigned*)g_hgh;

    float2 q = g_qs[node];
    float2 pself = g_ps[node];
    float t0 = pself.x * q.x, t1 = pself.y * q.y;
    float ws0 = t0 > 1.f ? pow5(t0) : t0;   // self-loop weights per head
    float ws1 = t1 > 1.f ? pow5(t1) : t1;
    float exs = head1 ? ws1 : ws0;

    unsigned hv = hgu[node * 32 + lane];
    float2 hf = __half22float2(*(const __half2*)&hv);
    float accx = exs * hf.x, accy = exs * hf.y;
    float acc2x = 0.f, acc2y = 0.f;
    float sA_acc = 0.f, sB_acc = 0.f;

    int off = g_off[node], deg = g_deg[node];
    for (int base = 0; base < deg; base += 32) {
        int cnt = min(32, deg - base);
        bool valid = lane < cnt;
        int r_l = g_csr[off + base + (valid ? lane : 0)];
        float2 pl = g_ps[r_l];
        float tA = pl.x * q.x, tB = pl.y * q.y;
        float exA = tA > 1.f ? pow5(tA) : tA;
        float exB = tB > 1.f ? pow5(tB) : tB;
        if (!valid) { exA = 0.f; exB = 0.f; }
        sA_acc += exA;
        sB_acc += exB;
        int k = 0;
        for (; k + 3 < cnt; k += 4) {
            int r0 = __shfl_sync(0xffffffffu, r_l, k);
            int r1 = __shfl_sync(0xffffffffu, r_l, k + 1);
            int r2 = __shfl_sync(0xffffffffu, r_l, k + 2);
            int r3 = __shfl_sync(0xffffffffu, r_l, k + 3);
            unsigned h0 = hgu[r0 * 32 + lane];
            unsigned h1 = hgu[r1 * 32 + lane];
            unsigned h2 = hgu[r2 * 32 + lane];
            unsigned h3 = hgu[r3 * 32 + lane];
            float wA0 = __shfl_sync(0xffffffffu, exA, k);
            float wB0 = __shfl_sync(0xffffffffu, exB, k);
            float wA1 = __shfl_sync(0xffffffffu, exA, k + 1);
            float wB1 = __shfl_sync(0xffffffffu, exB, k + 1);
            float wA2 = __shfl_sync(0xffffffffu, exA, k + 2);
            float wB2 = __shfl_sync(0xffffffffu, exB, k + 2);
            float wA3 = __shfl_sync(0xffffffffu, exA, k + 3);
            float wB3 = __shfl_sync(0xffffffffu, exB, k + 3);
            float w0 = head1 ? wB0 : wA0;
            float w1 = head1 ? wB1 : wA1;
            float w2 = head1 ? wB2 : wA2;
            float w3 = head1 ? wB3 : wA3;
            float2 f0 = __half22float2(*(const __half2*)&h0);
            float2 f1 = __half22float2(*(const __half2*)&h1);
            float2 f2 = __half22float2(*(const __half2*)&h2);
            float2 f3 = __half22float2(*(const __half2*)&h3);
            accx  = fmaf(w0, f0.x, accx);
            accy  = fmaf(w0, f0.y, accy);
            acc2x = fmaf(w1, f1.x, acc2x);
            acc2y = fmaf(w1, f1.y, acc2y);
            accx  = fmaf(w2, f2.x, accx);
            accy  = fmaf(w2, f2.y, accy);
            acc2x = fmaf(w3, f3.x, acc2x);
            acc2y = fmaf(w3, f3.y, acc2y);
        }
        for (; k < cnt; k++) {
            int r0 = __shfl_sync(0xffffffffu, r_l, k);
            float wA0 = __shfl_sync(0xffffffffu, exA, k);
            float wB0 = __shfl_sync(0xffffffffu, exB, k);
            float w0 = head1 ? wB0 : wA0;
            unsigned h0 = hgu[r0 * 32 + lane];
            float2 f0 = __half22float2(*(const __half2*)&h0);
            accx = fmaf(w0, f0.x, accx);
            accy = fmaf(w0, f0.y, accy);
        }
    }
#pragma unroll
    for (int o = 16; o; o >>= 1) {
        sA_acc += __shfl_xor_sync(0xffffffffu, sA_acc, o);
        sB_acc += __shfl_xor_sync(0xffffffffu, sB_acc, o);
    }
    float st = (head1 ? sB_acc : sA_acc) + exs;
    float vx = (accx + acc2x) / st;
    float vy = (accy + acc2y) / st;

    float ox = __shfl_down_sync(0xffffffffu, vx, 16);
    float oy = __shfl_down_sync(0xffffffffu, vy, 16);
    float c0 = fmaxf(fmaf(0.5f, vx + ox, gat_b[ch]),     0.f);
    float c1 = fmaxf(fmaf(0.5f, vy + oy, gat_b[ch + 1]), 0.f);
    float zi = fmaf(c0, W2[ch], c1 * W2[ch + 1]);
#pragma unroll
    for (int o = 8; o; o >>= 1)
        zi += __shfl_down_sync(0xffffffffu, zi, o);
    if (lane == 0) g_z[node] = g_dinv[node] * zi;
}

// launch 7: warp/node GCN2 gather + output; tail-resets counters
__global__ void k_gcn2(float* __restrict__ out, const float* __restrict__ b2, int n) {
    int tid = threadIdx.x;
    int gid = blockIdx.x * blockDim.x + tid;
    int node = gid >> 5;
    int lane = tid & 31;
    if (node >= n) return;
    float s = (lane == 0) ? g_z[node] : 0.f;
    int off = g_off[node], end = off + g_deg[node];
    for (int j = off + lane; j < end; j += 32)
        s += g_z[g_csr[j]];
#pragma unroll
    for (int o = 16; o; o >>= 1)
        s += __shfl_down_sync(0xffffffffu, s, o);
    if (lane == 0) {
        out[node] = fmaf(g_dinv[node], s, b2[0]);
        g_deg[node] = 0;
    }
}

// ---------------- launch ----------------
extern "C" void kernel_launch(void* const* d_in, const int* in_sizes, int n_in,
                              void* d_out, int out_size) {
    const float* x    = (const float*)d_in[0];
    const void*  ei   = d_in[1];
    const float* W1   = (const float*)d_in[2];
    const float* b1   = (const float*)d_in[3];
    const float* Wg   = (const float*)d_in[4];
    const float* attS = (const float*)d_in[5];
    const float* attD = (const float*)d_in[6];
    const float* gb   = (const float*)d_in[7];
    const float* W2   = (const float*)d_in[8];
    const float* b2   = (const float*)d_in[9];
    float* out = (float*)d_out;

    int n = in_sizes[0] / 2;
    int E = in_sizes[1] / 2;
    const int T = 256;
    int nb = (n + 1023) / 1024;

    k_degcount<<<(E + T - 1) / T, T>>>(ei, E);
    k_scan1<<<nb, 1024>>>(n);
    k_scan23<<<nb, 1024>>>(x, n, nb);
    k_fill<<<(E + T - 1) / T, T>>>(ei, E);
    k_layer1<<<(n * 32 + T - 1) / T, T>>>(W1, b1, Wg, attS, attD, n);
    k_gat<<<(n * 32 + T - 1) / T, T>>>(gb, W2, n);
    k_gcn2<<<(n * 32 + T - 1) / T, T>>>(out, b2, n);
}